// round 3
// baseline (speedup 1.0000x reference)
#include <cuda_runtime.h>
#include <math.h>

#define BB   4
#define NPTS 16384
#define MPTS 4096
#define C1   128
#define C2   256
#define HCH  256
#define K1   384
#define NTOT (BB*NPTS)   // 65536

typedef unsigned long long u64;

// packed fp32 FMA: d = a*b + d (elementwise on fp32 pairs). Exact fp32 semantics.
#define FMA2(d, a, b) asm("fma.rn.f32x2 %0, %1, %2, %0;" : "+l"(d) : "l"(a), "l"(b))
#define DUP2(d, f)    asm("mov.b64 %0, {%1, %1};" : "=l"(d) : "r"(__float_as_uint(f)))

// ---------------- scratch (device globals: no allocation allowed) ----------------
__device__ float4 g_kpack[BB*MPTS];                         // 256 KB
__device__ float  g_kfT[(size_t)BB*MPTS*C2];                // 16.8 MB  known_feats point-major
__device__ float  g_featsT[(size_t)BB*NPTS*K1];             // 100.7 MB concat feats, point-major
__device__ int    g_idx3[NTOT*3];
__device__ float  g_w3[NTOT*3];
__device__ float  g_y1[(size_t)NTOT*HCH];                   // 67.1 MB  GEMM1 raw out, point-major
__device__ float  g_sum1[HCH], g_sq1[HCH], g_scale1[HCH], g_shift1[HCH];
__device__ float  g_sum2[HCH], g_sq2[HCH], g_scale2[HCH], g_shift2[HCH];

// ---------------- kernels ----------------

__global__ void zero_stats_kernel() {
    int t = threadIdx.x;
    g_sum1[t] = 0.f; g_sq1[t] = 0.f;
    g_sum2[t] = 0.f; g_sq2[t] = 0.f;
}

__global__ void prep_known_kernel(const float* __restrict__ known) {
    int t = blockIdx.x * 256 + threadIdx.x;
    if (t >= BB * MPTS) return;
    float x = known[t*3+0], y = known[t*3+1], z = known[t*3+2];
    g_kpack[t] = make_float4(x, y, z, x*x + y*y + z*z);
}

// known_feats [b][c][p] (256 x 4096) -> g_kfT [b][p][c]
__global__ void transpose_kf_kernel(const float* __restrict__ kf) {
    __shared__ float tile[32][33];
    int b = blockIdx.z;
    int p0 = blockIdx.x * 32, c0 = blockIdx.y * 32;
    const float* src = kf + (size_t)b * C2 * MPTS;
    float* dst = g_kfT + (size_t)b * MPTS * C2;
#pragma unroll
    for (int r = 0; r < 32; r += 8)
        tile[threadIdx.y + r][threadIdx.x] =
            src[(size_t)(c0 + threadIdx.y + r) * MPTS + p0 + threadIdx.x];
    __syncthreads();
#pragma unroll
    for (int r = 0; r < 32; r += 8)
        dst[(size_t)(p0 + threadIdx.y + r) * C2 + c0 + threadIdx.x] =
            tile[threadIdx.x][threadIdx.y + r];
}

// unknown_feats [b][c][i] (128 x 16384) -> g_featsT[b][i][256 + c]
__global__ void transpose_uf_kernel(const float* __restrict__ uf) {
    __shared__ float tile[32][33];
    int b = blockIdx.z;
    int i0 = blockIdx.x * 32, c0 = blockIdx.y * 32;
    const float* src = uf + (size_t)b * C1 * NPTS;
    float* dst = g_featsT + (size_t)b * NPTS * K1;
#pragma unroll
    for (int r = 0; r < 32; r += 8)
        tile[threadIdx.y + r][threadIdx.x] =
            src[(size_t)(c0 + threadIdx.y + r) * NPTS + i0 + threadIdx.x];
    __syncthreads();
#pragma unroll
    for (int r = 0; r < 32; r += 8)
        dst[(size_t)(i0 + threadIdx.y + r) * K1 + C2 + c0 + threadIdx.x] =
            tile[threadIdx.x][threadIdx.y + r];
}

// exhaustive 3-NN: one thread per unknown point; knowns staged in smem (4 tiles of 1024)
__global__ void __launch_bounds__(128) three_nn_kernel(const float* __restrict__ unknown) {
    int g = blockIdx.x * 128 + threadIdx.x;          // 0..65535
    int b = g >> 14;
    float ux = unknown[g*3+0], uy = unknown[g*3+1], uz = unknown[g*3+2];
    float ca = -2.f * ux, cb = -2.f * uy, cc = -2.f * uz;
    float u2 = ux*ux + uy*uy + uz*uz;
    float s0 = 3.4e38f, s1 = 3.4e38f, s2 = 3.4e38f;
    int   i0 = 0, i1 = 0, i2 = 0;

    __shared__ float4 sk[1024];
    const float4* kp = g_kpack + b * MPTS;

    for (int t = 0; t < 4; t++) {
        __syncthreads();
        for (int q = threadIdx.x; q < 1024; q += 128) sk[q] = kp[t*1024 + q];
        __syncthreads();
#pragma unroll 4
        for (int jj = 0; jj < 1024; jj++) {
            float4 k4 = sk[jj];
            float s = fmaf(k4.x, ca, fmaf(k4.y, cb, fmaf(k4.z, cc, k4.w)));
            if (s < s2) {
                int j = t*1024 + jj;
                if (s < s1) {
                    s2 = s1; i2 = i1;
                    if (s < s0) { s1 = s0; i1 = i0; s0 = s; i0 = j; }
                    else        { s1 = s;  i1 = j; }
                } else { s2 = s; i2 = j; }
            }
        }
    }
    float d0 = s0 + u2, d1 = s1 + u2, d2 = s2 + u2;
    float r0 = 1.f / (d0 + 1e-8f), r1 = 1.f / (d1 + 1e-8f), r2 = 1.f / (d2 + 1e-8f);
    float rs = r0 + r1 + r2;
    g_idx3[g*3+0] = i0; g_idx3[g*3+1] = i1; g_idx3[g*3+2] = i2;
    g_w3[g*3+0] = r0 / rs; g_w3[g*3+1] = r1 / rs; g_w3[g*3+2] = r2 / rs;
}

// gather + weighted sum -> g_featsT[b][i][0..255]; one warp per point
__global__ void interp_kernel() {
    int warp = threadIdx.x >> 5, lane = threadIdx.x & 31;
    int g = blockIdx.x * 8 + warp;                   // 0..65535
    int b = g >> 14;
    int p0 = g_idx3[g*3+0], p1 = g_idx3[g*3+1], p2 = g_idx3[g*3+2];
    float w0 = g_w3[g*3+0], w1 = g_w3[g*3+1], w2 = g_w3[g*3+2];
    const float4* f0 = (const float4*)&g_kfT[((size_t)(b*MPTS + p0)) * C2];
    const float4* f1 = (const float4*)&g_kfT[((size_t)(b*MPTS + p1)) * C2];
    const float4* f2 = (const float4*)&g_kfT[((size_t)(b*MPTS + p2)) * C2];
    float4* dst = (float4*)&g_featsT[(size_t)g * K1];
#pragma unroll
    for (int h = 0; h < 2; h++) {
        int v = lane*2 + h;
        float4 a = f0[v], c = f1[v], d = f2[v];
        float4 r;
        r.x = fmaf(w0, a.x, fmaf(w1, c.x, w2 * d.x));
        r.y = fmaf(w0, a.y, fmaf(w1, c.y, w2 * d.y));
        r.z = fmaf(w0, a.z, fmaf(w1, c.z, w2 * d.z));
        r.w = fmaf(w0, a.w, fmaf(w1, c.w, w2 * d.w));
        dst[v] = r;
    }
}

// GEMM1: y1[j][o] = sum_c W1[o][c] * featsT[j][c]   (K=384), f32x2 packed math
__global__ void __launch_bounds__(256) gemm1_kernel(const float* __restrict__ W1) {
    __shared__ __align__(16) float sW[16][128];
    __shared__ __align__(16) float sF[16][128];
    int j0 = blockIdx.x * 128;
    int o0 = blockIdx.y * 128;
    int tid = threadIdx.x;
    int to = tid & 15, tj = tid >> 4;
    int lr = tid >> 2;            // 0..63
    int lc = (tid & 3) * 4;       // 0,4,8,12
    u64 acc2[8][4];               // acc[r][c] pairs along c
#pragma unroll
    for (int r = 0; r < 8; r++)
#pragma unroll
        for (int c = 0; c < 4; c++) acc2[r][c] = 0ull;

    for (int kc = 0; kc < K1; kc += 16) {
#pragma unroll
        for (int h = 0; h < 2; h++) {
            int row = lr + h*64;
            float4 v = *(const float4*)&W1[(size_t)(o0 + row) * K1 + kc + lc];
            sW[lc+0][row] = v.x; sW[lc+1][row] = v.y; sW[lc+2][row] = v.z; sW[lc+3][row] = v.w;
            float4 f = *(const float4*)&g_featsT[(size_t)(j0 + row) * K1 + kc + lc];
            sF[lc+0][row] = f.x; sF[lc+1][row] = f.y; sF[lc+2][row] = f.z; sF[lc+3][row] = f.w;
        }
        __syncthreads();
#pragma unroll
        for (int k = 0; k < 16; k++) {
            u64 A[4];
            {
                ulonglong2 t0 = *(const ulonglong2*)&sW[k][to*8];
                ulonglong2 t1 = *(const ulonglong2*)&sW[k][to*8+4];
                A[0] = t0.x; A[1] = t0.y; A[2] = t1.x; A[3] = t1.y;
            }
            float bv[8];
            ((float4*)bv)[0] = *(const float4*)&sF[k][tj*8];
            ((float4*)bv)[1] = *(const float4*)&sF[k][tj*8+4];
#pragma unroll
            for (int r = 0; r < 8; r++) {
                u64 bd; DUP2(bd, bv[r]);
#pragma unroll
                for (int c = 0; c < 4; c++)
                    FMA2(acc2[r][c], A[c], bd);
            }
        }
        __syncthreads();
    }
#pragma unroll
    for (int r = 0; r < 8; r++) {
        float2 p0 = *(float2*)&acc2[r][0];
        float2 p1 = *(float2*)&acc2[r][1];
        float2 p2 = *(float2*)&acc2[r][2];
        float2 p3 = *(float2*)&acc2[r][3];
        float* dst = &g_y1[(size_t)(j0 + tj*8 + r) * HCH + o0 + to*8];
        *(float4*)dst       = make_float4(p0.x, p0.y, p1.x, p1.y);
        *(float4*)(dst + 4) = make_float4(p2.x, p2.y, p3.x, p3.y);
    }
}

// per-channel sums over y1 (point-major)
__global__ void stats1_kernel() {
    int o = threadIdx.x;
    size_t j0 = (size_t)blockIdx.x * 256;
    const float* p = g_y1 + j0 * HCH + o;
    float s = 0.f, q = 0.f;
    for (int r = 0; r < 256; r++) {
        float v = p[(size_t)r * HCH];
        s += v; q = fmaf(v, v, q);
    }
    atomicAdd(&g_sum1[o], s);
    atomicAdd(&g_sq1[o], q);
}

// which==1 -> BN1 params, which==2 -> BN2 params. Globals referenced from
// device code only (host-side references to __device__ symbols are invalid).
__global__ void finalize_kernel(const float* __restrict__ gamma,
                                const float* __restrict__ beta,
                                int which) {
    int o = threadIdx.x;
    const float invN = 1.f / (float)NTOT;
    float s  = (which == 1) ? g_sum1[o] : g_sum2[o];
    float q  = (which == 1) ? g_sq1[o]  : g_sq2[o];
    float mu  = s * invN;
    float var = q * invN - mu * mu;
    float sc  = gamma[o] * rsqrtf(var + 1e-5f);
    float sh  = fmaf(-mu, sc, beta[o]);
    if (which == 1) { g_scale1[o] = sc; g_shift1[o] = sh; }
    else            { g_scale2[o] = sc; g_shift2[o] = sh; }
}

// GEMM2: out_raw[b][o][i] = sum_c W2[o][c] * relu(bn1(y1[j][c]))  (K=256), f32x2, channel-major out
__global__ void __launch_bounds__(256) gemm2_kernel(const float* __restrict__ W2,
                                                    float* __restrict__ out) {
    __shared__ __align__(16) float sW[16][128];
    __shared__ __align__(16) float sF[16][128];
    int j0 = blockIdx.x * 128;
    int o0 = blockIdx.y * 128;
    int tid = threadIdx.x;
    int to = tid & 15, tj = tid >> 4;
    int lr = tid >> 2;
    int lc = (tid & 3) * 4;
    u64 acc2[8][4];
#pragma unroll
    for (int r = 0; r < 8; r++)
#pragma unroll
        for (int c = 0; c < 4; c++) acc2[r][c] = 0ull;

    for (int kc = 0; kc < HCH; kc += 16) {
        int cbase = kc + lc;
        float sc0 = g_scale1[cbase+0], sh0 = g_shift1[cbase+0];
        float sc1 = g_scale1[cbase+1], sh1 = g_shift1[cbase+1];
        float sc2 = g_scale1[cbase+2], sh2 = g_shift1[cbase+2];
        float sc3 = g_scale1[cbase+3], sh3 = g_shift1[cbase+3];
#pragma unroll
        for (int h = 0; h < 2; h++) {
            int row = lr + h*64;
            float4 v = *(const float4*)&W2[(size_t)(o0 + row) * HCH + kc + lc];
            sW[lc+0][row] = v.x; sW[lc+1][row] = v.y; sW[lc+2][row] = v.z; sW[lc+3][row] = v.w;
            float4 f = *(const float4*)&g_y1[(size_t)(j0 + row) * HCH + cbase];
            sF[lc+0][row] = fmaxf(0.f, fmaf(f.x, sc0, sh0));
            sF[lc+1][row] = fmaxf(0.f, fmaf(f.y, sc1, sh1));
            sF[lc+2][row] = fmaxf(0.f, fmaf(f.z, sc2, sh2));
            sF[lc+3][row] = fmaxf(0.f, fmaf(f.w, sc3, sh3));
        }
        __syncthreads();
#pragma unroll
        for (int k = 0; k < 16; k++) {
            u64 A[4];
            {
                ulonglong2 t0 = *(const ulonglong2*)&sW[k][to*8];
                ulonglong2 t1 = *(const ulonglong2*)&sW[k][to*8+4];
                A[0] = t0.x; A[1] = t0.y; A[2] = t1.x; A[3] = t1.y;
            }
            float bv[8];
            ((float4*)bv)[0] = *(const float4*)&sF[k][tj*8];
            ((float4*)bv)[1] = *(const float4*)&sF[k][tj*8+4];
#pragma unroll
            for (int r = 0; r < 8; r++) {
                u64 bd; DUP2(bd, bv[r]);
#pragma unroll
                for (int c = 0; c < 4; c++)
                    FMA2(acc2[r][c], A[c], bd);
            }
        }
        __syncthreads();
    }
    // transposed epilogue: out[(b*256 + o) * 16384 + i], raw (BN2 applied later)
    int j = j0 + tj*8;               // 8 consecutive j owned by this thread
    int b = j >> 14;
    int i = j & (NPTS - 1);
    float accf[8][8];
#pragma unroll
    for (int r = 0; r < 8; r++) {
#pragma unroll
        for (int c = 0; c < 4; c++) {
            float2 p = *(float2*)&acc2[r][c];
            accf[r][2*c+0] = p.x;
            accf[r][2*c+1] = p.y;
        }
    }
#pragma unroll
    for (int c = 0; c < 8; c++) {
        int o = o0 + to*8 + c;
        float* dst = out + ((size_t)(b * HCH + o)) * NPTS + i;
        *(float4*)dst       = make_float4(accf[0][c], accf[1][c], accf[2][c], accf[3][c]);
        *(float4*)(dst + 4) = make_float4(accf[4][c], accf[5][c], accf[6][c], accf[7][c]);
    }
}

// per-channel sums over channel-major raw output
__global__ void stats2_kernel(const float* __restrict__ y2) {
    int row = blockIdx.x;            // b*256 + o
    int o = row & 255;
    const float* p = y2 + (size_t)row * NPTS;
    float s = 0.f, q = 0.f;
    for (int i = threadIdx.x; i < NPTS; i += 256) {
        float v = p[i];
        s += v; q = fmaf(v, v, q);
    }
    __shared__ float ss[256], sq[256];
    ss[threadIdx.x] = s; sq[threadIdx.x] = q;
    __syncthreads();
    for (int w = 128; w > 0; w >>= 1) {
        if (threadIdx.x < w) { ss[threadIdx.x] += ss[threadIdx.x+w]; sq[threadIdx.x] += sq[threadIdx.x+w]; }
        __syncthreads();
    }
    if (threadIdx.x == 0) {
        atomicAdd(&g_sum2[o], ss[0]);
        atomicAdd(&g_sq2[o], sq[0]);
    }
}

// in-place BN2 + ReLU on channel-major output
__global__ void bnrelu_out_kernel(float* __restrict__ out) {
    size_t t = (size_t)blockIdx.x * 256 + threadIdx.x;   // float4 index
    int o = (int)((t >> 12) & 255);                      // 4096 float4 per row
    float sc = g_scale2[o], sh = g_shift2[o];
    float4 v = ((float4*)out)[t];
    v.x = fmaxf(0.f, fmaf(v.x, sc, sh));
    v.y = fmaxf(0.f, fmaf(v.y, sc, sh));
    v.z = fmaxf(0.f, fmaf(v.z, sc, sh));
    v.w = fmaxf(0.f, fmaf(v.w, sc, sh));
    ((float4*)out)[t] = v;
}

// ---------------- launch ----------------
extern "C" void kernel_launch(void* const* d_in, const int* in_sizes, int n_in,
                              void* d_out, int out_size) {
    const float* unknown       = (const float*)d_in[0];
    const float* known         = (const float*)d_in[1];
    const float* unknown_feats = (const float*)d_in[2];
    const float* known_feats   = (const float*)d_in[3];
    const float* W1            = (const float*)d_in[4];
    const float* gamma1        = (const float*)d_in[5];
    const float* beta1         = (const float*)d_in[6];
    const float* W2            = (const float*)d_in[7];
    const float* gamma2        = (const float*)d_in[8];
    const float* beta2         = (const float*)d_in[9];
    float* out = (float*)d_out;

    // ordered so gemm1 is the 6th launch (ncu -s 5 -c 1 window)
    prep_known_kernel<<<(BB*MPTS + 255)/256, 256>>>(known);
    transpose_kf_kernel<<<dim3(MPTS/32, C2/32, BB), dim3(32, 8)>>>(known_feats);
    transpose_uf_kernel<<<dim3(NPTS/32, C1/32, BB), dim3(32, 8)>>>(unknown_feats);
    three_nn_kernel<<<NTOT/128, 128>>>(unknown);
    interp_kernel<<<NTOT/8, 256>>>();
    gemm1_kernel<<<dim3(NTOT/128, HCH/128), 256>>>(W1);
    zero_stats_kernel<<<1, 256>>>();
    stats1_kernel<<<NTOT/256, 256>>>();
    finalize_kernel<<<1, 256>>>(gamma1, beta1, 1);
    gemm2_kernel<<<dim3(NTOT/128, HCH/128), 256>>>(W2, out);
    stats2_kernel<<<BB*HCH, 256>>>(out);
    finalize_kernel<<<1, 256>>>(gamma2, beta2, 2);
    bnrelu_out_kernel<<<(BB*HCH*(NPTS/4))/256, 256>>>(out);
}

// round 4
// speedup vs baseline: 1.0058x; 1.0058x over previous
#include <cuda_runtime.h>
#include <math.h>

#define BB   4
#define NPTS 16384
#define MPTS 4096
#define C1   128
#define C2   256
#define HCH  256
#define K1   384
#define NTOT (BB*NPTS)   // 65536

typedef unsigned long long u64;

// packed fp32 FMA: d = a*b + d (elementwise on fp32 pairs). Exact fp32 semantics.
#define FMA2(d, a, b) asm("fma.rn.f32x2 %0, %1, %2, %0;" : "+l"(d) : "l"(a), "l"(b))
#define DUP2(d, f)    asm("mov.b64 %0, {%1, %1};" : "=l"(d) : "r"(__float_as_uint(f)))

// ---------------- scratch (device globals: no allocation allowed) ----------------
__device__ float  g_kfT[(size_t)BB*MPTS*C2];                // 16.8 MB  known_feats point-major
__device__ float  g_featsT[(size_t)BB*NPTS*K1];             // 100.7 MB concat feats, point-major
__device__ float  g_ps[NTOT*12];                            // partial top-3 dists (4 tiles)
__device__ int    g_pi[NTOT*12];                            // partial top-3 indices
__device__ float  g_y1[(size_t)NTOT*HCH];                   // 67.1 MB  GEMM1 raw out, point-major
__device__ float  g_sum1[HCH], g_sq1[HCH], g_scale1[HCH], g_shift1[HCH];
__device__ float  g_sum2[HCH], g_sq2[HCH], g_scale2[HCH], g_shift2[HCH];

// ---------------- kernels ----------------

// fused transposes:
//  blockIdx.y <  4 : unknown_feats [b][c][i] (128 x 16384) -> g_featsT[b][i][256+c]
//  blockIdx.y >= 4 : known_feats   [b][c][p] (256 x 4096)  -> g_kfT[b][p][c]   (x < 128 only)
__global__ void fused_transpose_kernel(const float* __restrict__ uf,
                                       const float* __restrict__ kf) {
    __shared__ float tile[32][33];
    int b = blockIdx.z;
    if (blockIdx.y < 4) {
        int i0 = blockIdx.x * 32, c0 = blockIdx.y * 32;
        const float* src = uf + (size_t)b * C1 * NPTS;
        float* dst = g_featsT + (size_t)b * NPTS * K1;
#pragma unroll
        for (int r = 0; r < 32; r += 8)
            tile[threadIdx.y + r][threadIdx.x] =
                src[(size_t)(c0 + threadIdx.y + r) * NPTS + i0 + threadIdx.x];
        __syncthreads();
#pragma unroll
        for (int r = 0; r < 32; r += 8)
            dst[(size_t)(i0 + threadIdx.y + r) * K1 + C2 + c0 + threadIdx.x] =
                tile[threadIdx.x][threadIdx.y + r];
    } else {
        if (blockIdx.x >= MPTS/32) return;
        int p0 = blockIdx.x * 32, c0 = (blockIdx.y - 4) * 32;
        const float* src = kf + (size_t)b * C2 * MPTS;
        float* dst = g_kfT + (size_t)b * MPTS * C2;
#pragma unroll
        for (int r = 0; r < 32; r += 8)
            tile[threadIdx.y + r][threadIdx.x] =
                src[(size_t)(c0 + threadIdx.y + r) * MPTS + p0 + threadIdx.x];
        __syncthreads();
#pragma unroll
        for (int r = 0; r < 32; r += 8)
            dst[(size_t)(p0 + threadIdx.y + r) * C2 + c0 + threadIdx.x] =
                tile[threadIdx.x][threadIdx.y + r];
    }
}

// split-m 3-NN: blockIdx.x = point block (128 pts), blockIdx.y = m-tile (1024 knowns).
// Each thread tracks top-3 over its tile; partials to g_ps/g_pi.
__global__ void __launch_bounds__(128) three_nn_partial_kernel(
        const float* __restrict__ unknown, const float* __restrict__ known) {
    int tid = threadIdx.x;
    int g = blockIdx.x * 128 + tid;                  // 0..65535
    int t = blockIdx.y;                              // 0..3
    int b = g >> 14;

    __shared__ float4 sk[1024];
    const float* kb = known + ((size_t)b * MPTS + t * 1024) * 3;
    for (int q = tid; q < 1024; q += 128) {
        float x = kb[q*3+0], y = kb[q*3+1], z = kb[q*3+2];
        sk[q] = make_float4(x, y, z, x*x + y*y + z*z);
    }
    __syncthreads();

    float ux = unknown[g*3+0], uy = unknown[g*3+1], uz = unknown[g*3+2];
    float ca = -2.f * ux, cb = -2.f * uy, cc = -2.f * uz;
    float s0 = 3.4e38f, s1 = 3.4e38f, s2 = 3.4e38f;
    int   i0 = 0, i1 = 0, i2 = 0;

#pragma unroll 8
    for (int jj = 0; jj < 1024; jj++) {
        float4 k4 = sk[jj];
        float s = fmaf(k4.x, ca, fmaf(k4.y, cb, fmaf(k4.z, cc, k4.w)));
        if (s < s2) {
            if (s < s1) {
                s2 = s1; i2 = i1;
                if (s < s0) { s1 = s0; i1 = i0; s0 = s; i0 = jj; }
                else        { s1 = s;  i1 = jj; }
            } else { s2 = s; i2 = jj; }
        }
    }
    int base = t * 1024;
    int o = g * 12 + t * 3;
    g_ps[o+0] = s0; g_ps[o+1] = s1; g_ps[o+2] = s2;
    g_pi[o+0] = base + i0; g_pi[o+1] = base + i1; g_pi[o+2] = base + i2;
}

// merge partial top-3 (tile order preserved -> tie behavior matches sequential scan),
// compute weights, gather + weighted sum -> g_featsT[b][i][0..255]; one warp per point
__global__ void interp_merge_kernel(const float* __restrict__ unknown) {
    int warp = threadIdx.x >> 5, lane = threadIdx.x & 31;
    int g = blockIdx.x * 8 + warp;                   // 0..65535
    int b = g >> 14;

    float sl = (lane < 12) ? g_ps[g*12 + lane] : 3.4e38f;
    int   il = (lane < 12) ? g_pi[g*12 + lane] : 0;
    float s0 = 3.4e38f, s1 = 3.4e38f, s2 = 3.4e38f;
    int   i0 = 0, i1 = 0, i2 = 0;
#pragma unroll
    for (int j = 0; j < 12; j++) {
        float sj = __shfl_sync(0xffffffffu, sl, j);
        int   ij = __shfl_sync(0xffffffffu, il, j);
        if (sj < s2) {
            if (sj < s1) {
                s2 = s1; i2 = i1;
                if (sj < s0) { s1 = s0; i1 = i0; s0 = sj; i0 = ij; }
                else         { s1 = sj; i1 = ij; }
            } else { s2 = sj; i2 = ij; }
        }
    }
    float ux = unknown[g*3+0], uy = unknown[g*3+1], uz = unknown[g*3+2];
    float u2 = ux*ux + uy*uy + uz*uz;
    float d0 = s0 + u2, d1 = s1 + u2, d2 = s2 + u2;
    float r0 = 1.f / (d0 + 1e-8f), r1 = 1.f / (d1 + 1e-8f), r2 = 1.f / (d2 + 1e-8f);
    float rs = r0 + r1 + r2;
    float w0 = r0 / rs, w1 = r1 / rs, w2 = r2 / rs;

    const float4* f0 = (const float4*)&g_kfT[((size_t)(b*MPTS + i0)) * C2];
    const float4* f1 = (const float4*)&g_kfT[((size_t)(b*MPTS + i1)) * C2];
    const float4* f2 = (const float4*)&g_kfT[((size_t)(b*MPTS + i2)) * C2];
    float4* dst = (float4*)&g_featsT[(size_t)g * K1];
#pragma unroll
    for (int h = 0; h < 2; h++) {
        int v = lane*2 + h;
        float4 a = f0[v], c = f1[v], d = f2[v];
        float4 r;
        r.x = fmaf(w0, a.x, fmaf(w1, c.x, w2 * d.x));
        r.y = fmaf(w0, a.y, fmaf(w1, c.y, w2 * d.y));
        r.z = fmaf(w0, a.z, fmaf(w1, c.z, w2 * d.z));
        r.w = fmaf(w0, a.w, fmaf(w1, c.w, w2 * d.w));
        dst[v] = r;
    }
}

// GEMM1: y1[j][o] = sum_c W1[o][c] * featsT[j][c]   (K=384), f32x2 packed math
__global__ void __launch_bounds__(256) gemm1_kernel(const float* __restrict__ W1) {
    __shared__ __align__(16) float sW[16][128];
    __shared__ __align__(16) float sF[16][128];
    int j0 = blockIdx.x * 128;
    int o0 = blockIdx.y * 128;
    int tid = threadIdx.x;
    int to = tid & 15, tj = tid >> 4;
    int lr = tid >> 2;            // 0..63
    int lc = (tid & 3) * 4;       // 0,4,8,12
    u64 acc2[8][4];               // acc[r][c] pairs along c
#pragma unroll
    for (int r = 0; r < 8; r++)
#pragma unroll
        for (int c = 0; c < 4; c++) acc2[r][c] = 0ull;

    for (int kc = 0; kc < K1; kc += 16) {
#pragma unroll
        for (int h = 0; h < 2; h++) {
            int row = lr + h*64;
            float4 v = *(const float4*)&W1[(size_t)(o0 + row) * K1 + kc + lc];
            sW[lc+0][row] = v.x; sW[lc+1][row] = v.y; sW[lc+2][row] = v.z; sW[lc+3][row] = v.w;
            float4 f = *(const float4*)&g_featsT[(size_t)(j0 + row) * K1 + kc + lc];
            sF[lc+0][row] = f.x; sF[lc+1][row] = f.y; sF[lc+2][row] = f.z; sF[lc+3][row] = f.w;
        }
        __syncthreads();
#pragma unroll
        for (int k = 0; k < 16; k++) {
            u64 A[4];
            {
                ulonglong2 t0 = *(const ulonglong2*)&sW[k][to*8];
                ulonglong2 t1 = *(const ulonglong2*)&sW[k][to*8+4];
                A[0] = t0.x; A[1] = t0.y; A[2] = t1.x; A[3] = t1.y;
            }
            float bv[8];
            ((float4*)bv)[0] = *(const float4*)&sF[k][tj*8];
            ((float4*)bv)[1] = *(const float4*)&sF[k][tj*8+4];
#pragma unroll
            for (int r = 0; r < 8; r++) {
                u64 bd; DUP2(bd, bv[r]);
#pragma unroll
                for (int c = 0; c < 4; c++)
                    FMA2(acc2[r][c], A[c], bd);
            }
        }
        __syncthreads();
    }
#pragma unroll
    for (int r = 0; r < 8; r++) {
        float2 p0 = *(float2*)&acc2[r][0];
        float2 p1 = *(float2*)&acc2[r][1];
        float2 p2 = *(float2*)&acc2[r][2];
        float2 p3 = *(float2*)&acc2[r][3];
        float* dst = &g_y1[(size_t)(j0 + tj*8 + r) * HCH + o0 + to*8];
        *(float4*)dst       = make_float4(p0.x, p0.y, p1.x, p1.y);
        *(float4*)(dst + 4) = make_float4(p2.x, p2.y, p3.x, p3.y);
    }
}

__global__ void zero_stats_kernel() {
    int t = threadIdx.x;
    g_sum1[t] = 0.f; g_sq1[t] = 0.f;
    g_sum2[t] = 0.f; g_sq2[t] = 0.f;
}

// per-channel sums over y1 (point-major)
__global__ void stats1_kernel() {
    int o = threadIdx.x;
    size_t j0 = (size_t)blockIdx.x * 256;
    const float* p = g_y1 + j0 * HCH + o;
    float s = 0.f, q = 0.f;
    for (int r = 0; r < 256; r++) {
        float v = p[(size_t)r * HCH];
        s += v; q = fmaf(v, v, q);
    }
    atomicAdd(&g_sum1[o], s);
    atomicAdd(&g_sq1[o], q);
}

// which==1 -> BN1 params, which==2 -> BN2 params. Globals referenced from
// device code only (host-side references to __device__ symbols are invalid).
__global__ void finalize_kernel(const float* __restrict__ gamma,
                                const float* __restrict__ beta,
                                int which) {
    int o = threadIdx.x;
    const float invN = 1.f / (float)NTOT;
    float s  = (which == 1) ? g_sum1[o] : g_sum2[o];
    float q  = (which == 1) ? g_sq1[o]  : g_sq2[o];
    float mu  = s * invN;
    float var = q * invN - mu * mu;
    float sc  = gamma[o] * rsqrtf(var + 1e-5f);
    float sh  = fmaf(-mu, sc, beta[o]);
    if (which == 1) { g_scale1[o] = sc; g_shift1[o] = sh; }
    else            { g_scale2[o] = sc; g_shift2[o] = sh; }
}

// GEMM2: out_raw[b][o][i] = sum_c W2[o][c] * relu(bn1(y1[j][c]))  (K=256), f32x2, channel-major out
__global__ void __launch_bounds__(256) gemm2_kernel(const float* __restrict__ W2,
                                                    float* __restrict__ out) {
    __shared__ __align__(16) float sW[16][128];
    __shared__ __align__(16) float sF[16][128];
    int j0 = blockIdx.x * 128;
    int o0 = blockIdx.y * 128;
    int tid = threadIdx.x;
    int to = tid & 15, tj = tid >> 4;
    int lr = tid >> 2;
    int lc = (tid & 3) * 4;
    u64 acc2[8][4];
#pragma unroll
    for (int r = 0; r < 8; r++)
#pragma unroll
        for (int c = 0; c < 4; c++) acc2[r][c] = 0ull;

    for (int kc = 0; kc < HCH; kc += 16) {
        int cbase = kc + lc;
        float sc0 = g_scale1[cbase+0], sh0 = g_shift1[cbase+0];
        float sc1 = g_scale1[cbase+1], sh1 = g_shift1[cbase+1];
        float sc2 = g_scale1[cbase+2], sh2 = g_shift1[cbase+2];
        float sc3 = g_scale1[cbase+3], sh3 = g_shift1[cbase+3];
#pragma unroll
        for (int h = 0; h < 2; h++) {
            int row = lr + h*64;
            float4 v = *(const float4*)&W2[(size_t)(o0 + row) * HCH + kc + lc];
            sW[lc+0][row] = v.x; sW[lc+1][row] = v.y; sW[lc+2][row] = v.z; sW[lc+3][row] = v.w;
            float4 f = *(const float4*)&g_y1[(size_t)(j0 + row) * HCH + cbase];
            sF[lc+0][row] = fmaxf(0.f, fmaf(f.x, sc0, sh0));
            sF[lc+1][row] = fmaxf(0.f, fmaf(f.y, sc1, sh1));
            sF[lc+2][row] = fmaxf(0.f, fmaf(f.z, sc2, sh2));
            sF[lc+3][row] = fmaxf(0.f, fmaf(f.w, sc3, sh3));
        }
        __syncthreads();
#pragma unroll
        for (int k = 0; k < 16; k++) {
            u64 A[4];
            {
                ulonglong2 t0 = *(const ulonglong2*)&sW[k][to*8];
                ulonglong2 t1 = *(const ulonglong2*)&sW[k][to*8+4];
                A[0] = t0.x; A[1] = t0.y; A[2] = t1.x; A[3] = t1.y;
            }
            float bv[8];
            ((float4*)bv)[0] = *(const float4*)&sF[k][tj*8];
            ((float4*)bv)[1] = *(const float4*)&sF[k][tj*8+4];
#pragma unroll
            for (int r = 0; r < 8; r++) {
                u64 bd; DUP2(bd, bv[r]);
#pragma unroll
                for (int c = 0; c < 4; c++)
                    FMA2(acc2[r][c], A[c], bd);
            }
        }
        __syncthreads();
    }
    // transposed epilogue: out[(b*256 + o) * 16384 + i], raw (BN2 applied later)
    int j = j0 + tj*8;               // 8 consecutive j owned by this thread
    int b = j >> 14;
    int i = j & (NPTS - 1);
    float accf[8][8];
#pragma unroll
    for (int r = 0; r < 8; r++) {
#pragma unroll
        for (int c = 0; c < 4; c++) {
            float2 p = *(float2*)&acc2[r][c];
            accf[r][2*c+0] = p.x;
            accf[r][2*c+1] = p.y;
        }
    }
#pragma unroll
    for (int c = 0; c < 8; c++) {
        int o = o0 + to*8 + c;
        float* dst = out + ((size_t)(b * HCH + o)) * NPTS + i;
        *(float4*)dst       = make_float4(accf[0][c], accf[1][c], accf[2][c], accf[3][c]);
        *(float4*)(dst + 4) = make_float4(accf[4][c], accf[5][c], accf[6][c], accf[7][c]);
    }
}

// per-channel sums over channel-major raw output
__global__ void stats2_kernel(const float* __restrict__ y2) {
    int row = blockIdx.x;            // b*256 + o
    int o = row & 255;
    const float* p = y2 + (size_t)row * NPTS;
    float s = 0.f, q = 0.f;
    for (int i = threadIdx.x; i < NPTS; i += 256) {
        float v = p[i];
        s += v; q = fmaf(v, v, q);
    }
    __shared__ float ss[256], sq[256];
    ss[threadIdx.x] = s; sq[threadIdx.x] = q;
    __syncthreads();
    for (int w = 128; w > 0; w >>= 1) {
        if (threadIdx.x < w) { ss[threadIdx.x] += ss[threadIdx.x+w]; sq[threadIdx.x] += sq[threadIdx.x+w]; }
        __syncthreads();
    }
    if (threadIdx.x == 0) {
        atomicAdd(&g_sum2[o], ss[0]);
        atomicAdd(&g_sq2[o], sq[0]);
    }
}

// in-place BN2 + ReLU on channel-major output
__global__ void bnrelu_out_kernel(float* __restrict__ out) {
    size_t t = (size_t)blockIdx.x * 256 + threadIdx.x;   // float4 index
    int o = (int)((t >> 12) & 255);                      // 4096 float4 per row
    float sc = g_scale2[o], sh = g_shift2[o];
    float4 v = ((float4*)out)[t];
    v.x = fmaxf(0.f, fmaf(v.x, sc, sh));
    v.y = fmaxf(0.f, fmaf(v.y, sc, sh));
    v.z = fmaxf(0.f, fmaf(v.z, sc, sh));
    v.w = fmaxf(0.f, fmaf(v.w, sc, sh));
    ((float4*)out)[t] = v;
}

// ---------------- launch ----------------
extern "C" void kernel_launch(void* const* d_in, const int* in_sizes, int n_in,
                              void* d_out, int out_size) {
    const float* unknown       = (const float*)d_in[0];
    const float* known         = (const float*)d_in[1];
    const float* unknown_feats = (const float*)d_in[2];
    const float* known_feats   = (const float*)d_in[3];
    const float* W1            = (const float*)d_in[4];
    const float* gamma1        = (const float*)d_in[5];
    const float* beta1         = (const float*)d_in[6];
    const float* W2            = (const float*)d_in[7];
    const float* gamma2        = (const float*)d_in[8];
    const float* beta2         = (const float*)d_in[9];
    float* out = (float*)d_out;

    // gemm1 placed at launch slot 4 (empirically the ncu-captured launch)
    fused_transpose_kernel<<<dim3(NPTS/32, 12, BB), dim3(32, 8)>>>(unknown_feats, known_feats);
    three_nn_partial_kernel<<<dim3(NTOT/128, 4), 128>>>(unknown, known);
    interp_merge_kernel<<<NTOT/8, 256>>>(unknown);
    gemm1_kernel<<<dim3(NTOT/128, HCH/128), 256>>>(W1);
    zero_stats_kernel<<<1, 256>>>();
    stats1_kernel<<<NTOT/256, 256>>>();
    finalize_kernel<<<1, 256>>>(gamma1, beta1, 1);
    gemm2_kernel<<<dim3(NTOT/128, HCH/128), 256>>>(W2, out);
    stats2_kernel<<<BB*HCH, 256>>>(out);
    finalize_kernel<<<1, 256>>>(gamma2, beta2, 2);
    bnrelu_out_kernel<<<(BB*HCH*(NPTS/4))/256, 256>>>(out);
}

// round 5
// speedup vs baseline: 1.1845x; 1.1777x over previous
#include <cuda_runtime.h>
#include <math.h>

#define BB   4
#define NPTS 16384
#define MPTS 4096
#define C1   128
#define C2   256
#define HCH  256
#define K1   384
#define NTOT (BB*NPTS)   // 65536

typedef unsigned long long u64;

// packed fp32 FMA: d = a*b + d (elementwise on fp32 pairs). Exact fp32 semantics.
#define FMA2(d, a, b) asm("fma.rn.f32x2 %0, %1, %2, %0;" : "+l"(d) : "l"(a), "l"(b))
#define DUP2(d, f)    asm("mov.b64 %0, {%1, %1};" : "=l"(d) : "r"(__float_as_uint(f)))

// ---------------- scratch (device globals) ----------------
__device__ float g_kfT[(size_t)BB*MPTS*C2];     // 16.8 MB known_feats point-major (for gather)
__device__ float g_icm[(size_t)C2*NTOT];        // 67 MB interp result, channel-major [c][j]
__device__ float g_y1cm[(size_t)HCH*NTOT];      // 67 MB gemm1 raw out, channel-major [o][j]
__device__ float g_W1T[K1*HCH];                 // W1 transposed [k][o]
__device__ float g_W2T[HCH*HCH];                // W2 transposed [k][o]
__device__ float g_ps[NTOT*12];
__device__ int   g_pi[NTOT*12];
__device__ float g_sum1[HCH], g_sq1[HCH], g_scale1[HCH], g_shift1[HCH];
__device__ float g_sum2[HCH], g_sq2[HCH], g_scale2[HCH], g_shift2[HCH];

// ---------------- prep: kf transpose + W transposes + stat zeroing ----------------
// grid (128, 10, BB), block (32, 8)
__global__ void prep_kernel(const float* __restrict__ kf,
                            const float* __restrict__ W1,
                            const float* __restrict__ W2) {
    __shared__ float tile[32][33];
    int tx = threadIdx.x, ty = threadIdx.y;
    int b = blockIdx.z, y = blockIdx.y, x = blockIdx.x;
    if (y < 8) {
        // known_feats [b][c][p] -> g_kfT [b][p][c]
        int p0 = x * 32, c0 = y * 32;
        const float* src = kf + (size_t)b * C2 * MPTS;
        float* dst = g_kfT + (size_t)b * MPTS * C2;
#pragma unroll
        for (int r = 0; r < 32; r += 8)
            tile[ty + r][tx] = src[(size_t)(c0 + ty + r) * MPTS + p0 + tx];
        __syncthreads();
#pragma unroll
        for (int r = 0; r < 32; r += 8)
            dst[(size_t)(p0 + ty + r) * C2 + c0 + tx] = tile[tx][ty + r];
    } else if (b == 0) {
        if (y == 8) {
            if (x >= 96) return;                 // 12 c-tiles x 8 o-tiles
            int c0 = (x >> 3) * 32, o0 = (x & 7) * 32;
#pragma unroll
            for (int r = 0; r < 32; r += 8)
                tile[ty + r][tx] = W1[(size_t)(o0 + ty + r) * K1 + c0 + tx];
            __syncthreads();
#pragma unroll
            for (int r = 0; r < 32; r += 8)
                g_W1T[(size_t)(c0 + ty + r) * HCH + o0 + tx] = tile[tx][ty + r];
        } else {                                  // y == 9
            if (x < 64) {                         // 8 x 8 tiles
                int c0 = (x >> 3) * 32, o0 = (x & 7) * 32;
#pragma unroll
                for (int r = 0; r < 32; r += 8)
                    tile[ty + r][tx] = W2[(size_t)(o0 + ty + r) * HCH + c0 + tx];
                __syncthreads();
#pragma unroll
                for (int r = 0; r < 32; r += 8)
                    g_W2T[(size_t)(c0 + ty + r) * HCH + o0 + tx] = tile[tx][ty + r];
            } else if (x == 64) {
                int t = ty * 32 + tx;
                g_sum1[t] = 0.f; g_sq1[t] = 0.f;
                g_sum2[t] = 0.f; g_sq2[t] = 0.f;
            }
        }
    }
}

// ---------------- split-m 3-NN partials ----------------
__global__ void __launch_bounds__(128) three_nn_partial_kernel(
        const float* __restrict__ unknown, const float* __restrict__ known) {
    int tid = threadIdx.x;
    int g = blockIdx.x * 128 + tid;
    int t = blockIdx.y;                              // 0..3
    int b = g >> 14;

    __shared__ float4 sk[1024];
    const float* kb = known + ((size_t)b * MPTS + t * 1024) * 3;
    for (int q = tid; q < 1024; q += 128) {
        float x = kb[q*3+0], y = kb[q*3+1], z = kb[q*3+2];
        sk[q] = make_float4(x, y, z, x*x + y*y + z*z);
    }
    __syncthreads();

    float ux = unknown[g*3+0], uy = unknown[g*3+1], uz = unknown[g*3+2];
    float ca = -2.f * ux, cb = -2.f * uy, cc = -2.f * uz;
    float s0 = 3.4e38f, s1 = 3.4e38f, s2 = 3.4e38f;
    int   i0 = 0, i1 = 0, i2 = 0;

#pragma unroll 8
    for (int jj = 0; jj < 1024; jj++) {
        float4 k4 = sk[jj];
        float s = fmaf(k4.x, ca, fmaf(k4.y, cb, fmaf(k4.z, cc, k4.w)));
        if (s < s2) {
            if (s < s1) {
                s2 = s1; i2 = i1;
                if (s < s0) { s1 = s0; i1 = i0; s0 = s; i0 = jj; }
                else        { s1 = s;  i1 = jj; }
            } else { s2 = s; i2 = jj; }
        }
    }
    int base = t * 1024;
    int o = g * 12 + t * 3;
    g_ps[o+0] = s0; g_ps[o+1] = s1; g_ps[o+2] = s2;
    g_pi[o+0] = base + i0; g_pi[o+1] = base + i1; g_pi[o+2] = base + i2;
}

// ---------------- merge + gather + interpolate, channel-major output ----------------
// block: 256 threads handles 32 points
__global__ void __launch_bounds__(256) interp_merge_cm_kernel(const float* __restrict__ unknown) {
    __shared__ float sw0[32], sw1[32], sw2[32];
    __shared__ int   si0[32], si1[32], si2[32];
    __shared__ float tile[256][33];                  // [c][p]
    int tid = threadIdx.x;
    int j0 = blockIdx.x * 32;
    int b  = j0 >> 14;

    if (tid < 32) {
        int g = j0 + tid;
        float s0 = 3.4e38f, s1 = 3.4e38f, s2 = 3.4e38f;
        int   i0 = 0, i1 = 0, i2 = 0;
#pragma unroll
        for (int t = 0; t < 12; t++) {
            float sj = g_ps[g*12 + t];
            int   ij = g_pi[g*12 + t];
            if (sj < s2) {
                if (sj < s1) {
                    s2 = s1; i2 = i1;
                    if (sj < s0) { s1 = s0; i1 = i0; s0 = sj; i0 = ij; }
                    else         { s1 = sj; i1 = ij; }
                } else { s2 = sj; i2 = ij; }
            }
        }
        float ux = unknown[g*3+0], uy = unknown[g*3+1], uz = unknown[g*3+2];
        float u2 = ux*ux + uy*uy + uz*uz;
        float d0 = s0 + u2, d1 = s1 + u2, d2 = s2 + u2;
        float r0 = 1.f / (d0 + 1e-8f), r1 = 1.f / (d1 + 1e-8f), r2 = 1.f / (d2 + 1e-8f);
        float rs = r0 + r1 + r2;
        sw0[tid] = r0 / rs; sw1[tid] = r1 / rs; sw2[tid] = r2 / rs;
        si0[tid] = i0; si1[tid] = i1; si2[tid] = i2;
    }
    __syncthreads();

    // gather: thread (p = tid&31, q = tid>>5) handles point p, channels q*32..q*32+31
    int p = tid & 31, q = tid >> 5;
    float w0 = sw0[p], w1 = sw1[p], w2 = sw2[p];
    const float4* f0 = (const float4*)&g_kfT[((size_t)(b*MPTS) + si0[p]) * C2];
    const float4* f1 = (const float4*)&g_kfT[((size_t)(b*MPTS) + si1[p]) * C2];
    const float4* f2 = (const float4*)&g_kfT[((size_t)(b*MPTS) + si2[p]) * C2];
#pragma unroll
    for (int v = 0; v < 8; v++) {
        int c4 = q * 8 + v;
        float4 a = f0[c4], c = f1[c4], d = f2[c4];
        int cc = c4 * 4;
        tile[cc+0][p] = fmaf(w0, a.x, fmaf(w1, c.x, w2 * d.x));
        tile[cc+1][p] = fmaf(w0, a.y, fmaf(w1, c.y, w2 * d.y));
        tile[cc+2][p] = fmaf(w0, a.z, fmaf(w1, c.z, w2 * d.z));
        tile[cc+3][p] = fmaf(w0, a.w, fmaf(w1, c.w, w2 * d.w));
    }
    __syncthreads();

    // write channel-major: 8 threads per channel row, coalesced 128B chunks
    int part = tid & 7;                               // 0..7 -> 4 floats each
    int crow = tid >> 3;                              // 0..31
#pragma unroll
    for (int rg = 0; rg < 8; rg++) {
        int c = rg * 32 + crow;
        float4 v = make_float4(tile[c][part*4+0], tile[c][part*4+1],
                               tile[c][part*4+2], tile[c][part*4+3]);
        *(float4*)(g_icm + (size_t)c * NTOT + j0 + part*4) = v;
    }
}

// ---------------- GEMM1: y1cm[o][j] = sum_c W1T[c][o] * feats_cm[c][j], fused stats ----------------
__global__ void __launch_bounds__(256, 2) gemm1_kernel(const float* __restrict__ uf) {
    __shared__ __align__(16) float sW[16][128];
    __shared__ __align__(16) float sF[16][128];
    __shared__ float bs[128], bq[128];
    int tid = threadIdx.x;
    int j0 = blockIdx.x * 128, o0 = blockIdx.y * 128;
    int b = j0 >> 14, i0 = j0 & (NPTS - 1);
    int lane = tid & 31, warp = tid >> 5;
    int lo = lane & 3, lj = lane >> 2;
    int warp_o = warp & 3, warp_j = warp >> 2;
    int oo = warp_o * 32 + lo * 8;                   // 0..127
    int jj = warp_j * 64 + lj * 8;                   // 0..127
    int lcol = (tid & 31) * 4;                       // loader col
    int lrow = tid >> 5;                             // loader row 0..7

    if (tid < 128) { bs[tid] = 0.f; bq[tid] = 0.f; }

    u64 acc2[8][4];
#pragma unroll
    for (int r = 0; r < 8; r++)
#pragma unroll
        for (int c = 0; c < 4; c++) acc2[r][c] = 0ull;

    float4 pw0, pw1, pf0, pf1;
    pw0 = *(const float4*)&g_W1T[(size_t)(lrow) * HCH + o0 + lcol];
    pw1 = *(const float4*)&g_W1T[(size_t)(8 + lrow) * HCH + o0 + lcol];
    pf0 = *(const float4*)&g_icm[(size_t)(lrow) * NTOT + j0 + lcol];
    pf1 = *(const float4*)&g_icm[(size_t)(8 + lrow) * NTOT + j0 + lcol];

    for (int kc = 0; kc < K1; kc += 16) {
        *(float4*)&sW[lrow][lcol]     = pw0;
        *(float4*)&sW[lrow + 8][lcol] = pw1;
        *(float4*)&sF[lrow][lcol]     = pf0;
        *(float4*)&sF[lrow + 8][lcol] = pf1;
        __syncthreads();
        int kn = kc + 16;
        if (kn < K1) {
            pw0 = *(const float4*)&g_W1T[(size_t)(kn + lrow) * HCH + o0 + lcol];
            pw1 = *(const float4*)&g_W1T[(size_t)(kn + 8 + lrow) * HCH + o0 + lcol];
            if (kn < C2) {
                pf0 = *(const float4*)&g_icm[(size_t)(kn + lrow) * NTOT + j0 + lcol];
                pf1 = *(const float4*)&g_icm[(size_t)(kn + 8 + lrow) * NTOT + j0 + lcol];
            } else {
                pf0 = *(const float4*)&uf[((size_t)b*C1 + (kn - C2 + lrow)) * NPTS + i0 + lcol];
                pf1 = *(const float4*)&uf[((size_t)b*C1 + (kn - C2 + 8 + lrow)) * NPTS + i0 + lcol];
            }
        }
#pragma unroll
        for (int k = 0; k < 16; k++) {
            u64 A[4];
            {
                ulonglong2 t0 = *(const ulonglong2*)&sW[k][oo];
                ulonglong2 t1 = *(const ulonglong2*)&sW[k][oo + 4];
                A[0] = t0.x; A[1] = t0.y; A[2] = t1.x; A[3] = t1.y;
            }
            float bv[8];
            ((float4*)bv)[0] = *(const float4*)&sF[k][jj];
            ((float4*)bv)[1] = *(const float4*)&sF[k][jj + 4];
#pragma unroll
            for (int r = 0; r < 8; r++) {
                u64 bd; DUP2(bd, bv[r]);
#pragma unroll
                for (int c = 0; c < 4; c++)
                    FMA2(acc2[r][c], A[c], bd);
            }
        }
        __syncthreads();
    }

    // epilogue: channel-major store + fused per-channel stats
    float accf[8][8];
#pragma unroll
    for (int r = 0; r < 8; r++)
#pragma unroll
        for (int c = 0; c < 4; c++) {
            float2 pp = *(float2*)&acc2[r][c];
            accf[r][2*c+0] = pp.x; accf[r][2*c+1] = pp.y;
        }
#pragma unroll
    for (int c8 = 0; c8 < 8; c8++) {
        int o = o0 + oo + c8;
        float v0=accf[0][c8], v1=accf[1][c8], v2=accf[2][c8], v3=accf[3][c8];
        float v4=accf[4][c8], v5=accf[5][c8], v6=accf[6][c8], v7=accf[7][c8];
        float s = v0+v1+v2+v3+v4+v5+v6+v7;
        float qq = fmaf(v0,v0, fmaf(v1,v1, fmaf(v2,v2, fmaf(v3,v3,
                   fmaf(v4,v4, fmaf(v5,v5, fmaf(v6,v6, v7*v7)))))));
#pragma unroll
        for (int m = 4; m <= 16; m <<= 1) {
            s  += __shfl_xor_sync(0xffffffffu, s, m);
            qq += __shfl_xor_sync(0xffffffffu, qq, m);
        }
        if (lj == 0) { atomicAdd(&bs[oo + c8], s); atomicAdd(&bq[oo + c8], qq); }
        float* dst = &g_y1cm[(size_t)o * NTOT + j0 + jj];
        *(float4*)dst       = make_float4(v0, v1, v2, v3);
        *(float4*)(dst + 4) = make_float4(v4, v5, v6, v7);
    }
    __syncthreads();
    if (tid < 128) {
        atomicAdd(&g_sum1[o0 + tid], bs[tid]);
        atomicAdd(&g_sq1[o0 + tid], bq[tid]);
    }
}

// which==1 -> BN1, which==2 -> BN2
__global__ void finalize_kernel(const float* __restrict__ gamma,
                                const float* __restrict__ beta,
                                int which) {
    int o = threadIdx.x;
    const float invN = 1.f / (float)NTOT;
    float s  = (which == 1) ? g_sum1[o] : g_sum2[o];
    float q  = (which == 1) ? g_sq1[o]  : g_sq2[o];
    float mu  = s * invN;
    float var = q * invN - mu * mu;
    float sc  = gamma[o] * rsqrtf(var + 1e-5f);
    float sh  = fmaf(-mu, sc, beta[o]);
    if (which == 1) { g_scale1[o] = sc; g_shift1[o] = sh; }
    else            { g_scale2[o] = sc; g_shift2[o] = sh; }
}

// ---------------- GEMM2: out_raw[b][o][i] = sum_c W2T[c][o]*relu(bn1(y1cm[c][j])), fused stats ----------------
__global__ void __launch_bounds__(256, 2) gemm2_kernel(float* __restrict__ out) {
    __shared__ __align__(16) float sW[16][128];
    __shared__ __align__(16) float sF[16][128];
    __shared__ float bs[128], bq[128];
    int tid = threadIdx.x;
    int j0 = blockIdx.x * 128, o0 = blockIdx.y * 128;
    int b = j0 >> 14, i0 = j0 & (NPTS - 1);
    int lane = tid & 31, warp = tid >> 5;
    int lo = lane & 3, lj = lane >> 2;
    int warp_o = warp & 3, warp_j = warp >> 2;
    int oo = warp_o * 32 + lo * 8;
    int jj = warp_j * 64 + lj * 8;
    int lcol = (tid & 31) * 4;
    int lrow = tid >> 5;

    if (tid < 128) { bs[tid] = 0.f; bq[tid] = 0.f; }

    u64 acc2[8][4];
#pragma unroll
    for (int r = 0; r < 8; r++)
#pragma unroll
        for (int c = 0; c < 4; c++) acc2[r][c] = 0ull;

    float4 pw0, pw1, pf0, pf1;
    {
        pw0 = *(const float4*)&g_W2T[(size_t)(lrow) * HCH + o0 + lcol];
        pw1 = *(const float4*)&g_W2T[(size_t)(8 + lrow) * HCH + o0 + lcol];
        float4 f0 = *(const float4*)&g_y1cm[(size_t)(lrow) * NTOT + j0 + lcol];
        float4 f1 = *(const float4*)&g_y1cm[(size_t)(8 + lrow) * NTOT + j0 + lcol];
        float sc0 = g_scale1[lrow],     sh0 = g_shift1[lrow];
        float sc1 = g_scale1[8 + lrow], sh1 = g_shift1[8 + lrow];
        pf0.x = fmaxf(0.f, fmaf(f0.x, sc0, sh0)); pf0.y = fmaxf(0.f, fmaf(f0.y, sc0, sh0));
        pf0.z = fmaxf(0.f, fmaf(f0.z, sc0, sh0)); pf0.w = fmaxf(0.f, fmaf(f0.w, sc0, sh0));
        pf1.x = fmaxf(0.f, fmaf(f1.x, sc1, sh1)); pf1.y = fmaxf(0.f, fmaf(f1.y, sc1, sh1));
        pf1.z = fmaxf(0.f, fmaf(f1.z, sc1, sh1)); pf1.w = fmaxf(0.f, fmaf(f1.w, sc1, sh1));
    }

    for (int kc = 0; kc < HCH; kc += 16) {
        *(float4*)&sW[lrow][lcol]     = pw0;
        *(float4*)&sW[lrow + 8][lcol] = pw1;
        *(float4*)&sF[lrow][lcol]     = pf0;
        *(float4*)&sF[lrow + 8][lcol] = pf1;
        __syncthreads();
        int kn = kc + 16;
        if (kn < HCH) {
            pw0 = *(const float4*)&g_W2T[(size_t)(kn + lrow) * HCH + o0 + lcol];
            pw1 = *(const float4*)&g_W2T[(size_t)(kn + 8 + lrow) * HCH + o0 + lcol];
            float4 f0 = *(const float4*)&g_y1cm[(size_t)(kn + lrow) * NTOT + j0 + lcol];
            float4 f1 = *(const float4*)&g_y1cm[(size_t)(kn + 8 + lrow) * NTOT + j0 + lcol];
            float sc0 = g_scale1[kn + lrow],     sh0 = g_shift1[kn + lrow];
            float sc1 = g_scale1[kn + 8 + lrow], sh1 = g_shift1[kn + 8 + lrow];
            pf0.x = fmaxf(0.f, fmaf(f0.x, sc0, sh0)); pf0.y = fmaxf(0.f, fmaf(f0.y, sc0, sh0));
            pf0.z = fmaxf(0.f, fmaf(f0.z, sc0, sh0)); pf0.w = fmaxf(0.f, fmaf(f0.w, sc0, sh0));
            pf1.x = fmaxf(0.f, fmaf(f1.x, sc1, sh1)); pf1.y = fmaxf(0.f, fmaf(f1.y, sc1, sh1));
            pf1.z = fmaxf(0.f, fmaf(f1.z, sc1, sh1)); pf1.w = fmaxf(0.f, fmaf(f1.w, sc1, sh1));
        }
#pragma unroll
        for (int k = 0; k < 16; k++) {
            u64 A[4];
            {
                ulonglong2 t0 = *(const ulonglong2*)&sW[k][oo];
                ulonglong2 t1 = *(const ulonglong2*)&sW[k][oo + 4];
                A[0] = t0.x; A[1] = t0.y; A[2] = t1.x; A[3] = t1.y;
            }
            float bv[8];
            ((float4*)bv)[0] = *(const float4*)&sF[k][jj];
            ((float4*)bv)[1] = *(const float4*)&sF[k][jj + 4];
#pragma unroll
            for (int r = 0; r < 8; r++) {
                u64 bd; DUP2(bd, bv[r]);
#pragma unroll
                for (int c = 0; c < 4; c++)
                    FMA2(acc2[r][c], A[c], bd);
            }
        }
        __syncthreads();
    }

    float accf[8][8];
#pragma unroll
    for (int r = 0; r < 8; r++)
#pragma unroll
        for (int c = 0; c < 4; c++) {
            float2 pp = *(float2*)&acc2[r][c];
            accf[r][2*c+0] = pp.x; accf[r][2*c+1] = pp.y;
        }
#pragma unroll
    for (int c8 = 0; c8 < 8; c8++) {
        int o = o0 + oo + c8;
        float v0=accf[0][c8], v1=accf[1][c8], v2=accf[2][c8], v3=accf[3][c8];
        float v4=accf[4][c8], v5=accf[5][c8], v6=accf[6][c8], v7=accf[7][c8];
        float s = v0+v1+v2+v3+v4+v5+v6+v7;
        float qq = fmaf(v0,v0, fmaf(v1,v1, fmaf(v2,v2, fmaf(v3,v3,
                   fmaf(v4,v4, fmaf(v5,v5, fmaf(v6,v6, v7*v7)))))));
#pragma unroll
        for (int m = 4; m <= 16; m <<= 1) {
            s  += __shfl_xor_sync(0xffffffffu, s, m);
            qq += __shfl_xor_sync(0xffffffffu, qq, m);
        }
        if (lj == 0) { atomicAdd(&bs[oo + c8], s); atomicAdd(&bq[oo + c8], qq); }
        float* dst = out + ((size_t)(b * HCH + o)) * NPTS + i0 + jj;
        *(float4*)dst       = make_float4(v0, v1, v2, v3);
        *(float4*)(dst + 4) = make_float4(v4, v5, v6, v7);
    }
    __syncthreads();
    if (tid < 128) {
        atomicAdd(&g_sum2[o0 + tid], bs[tid]);
        atomicAdd(&g_sq2[o0 + tid], bq[tid]);
    }
}

// in-place BN2 + ReLU on channel-major output
__global__ void bnrelu_out_kernel(float* __restrict__ out) {
    size_t t = (size_t)blockIdx.x * 256 + threadIdx.x;   // float4 index
    int o = (int)((t >> 12) & 255);
    float sc = g_scale2[o], sh = g_shift2[o];
    float4 v = ((float4*)out)[t];
    v.x = fmaxf(0.f, fmaf(v.x, sc, sh));
    v.y = fmaxf(0.f, fmaf(v.y, sc, sh));
    v.z = fmaxf(0.f, fmaf(v.z, sc, sh));
    v.w = fmaxf(0.f, fmaf(v.w, sc, sh));
    ((float4*)out)[t] = v;
}

// ---------------- launch ----------------
extern "C" void kernel_launch(void* const* d_in, const int* in_sizes, int n_in,
                              void* d_out, int out_size) {
    const float* unknown       = (const float*)d_in[0];
    const float* known         = (const float*)d_in[1];
    const float* unknown_feats = (const float*)d_in[2];
    const float* known_feats   = (const float*)d_in[3];
    const float* gamma1        = (const float*)d_in[5];
    const float* beta1         = (const float*)d_in[6];
    const float* W1            = (const float*)d_in[4];
    const float* W2            = (const float*)d_in[7];
    const float* gamma2        = (const float*)d_in[8];
    const float* beta2         = (const float*)d_in[9];
    float* out = (float*)d_out;

    // gemm1 at launch slot 4 (the ncu-captured launch)
    prep_kernel<<<dim3(128, 10, BB), dim3(32, 8)>>>(known_feats, W1, W2);
    three_nn_partial_kernel<<<dim3(NTOT/128, 4), 128>>>(unknown, known);
    interp_merge_cm_kernel<<<NTOT/32, 256>>>(unknown);
    gemm1_kernel<<<dim3(NTOT/128, HCH/128), 256>>>(unknown_feats);
    finalize_kernel<<<1, 256>>>(gamma1, beta1, 1);
    gemm2_kernel<<<dim3(NTOT/128, HCH/128), 256>>>(out);
    finalize_kernel<<<1, 256>>>(gamma2, beta2, 2);
    bnrelu_out_kernel<<<(BB*HCH*(NPTS/4))/256, 256>>>(out);
}

// round 7
// speedup vs baseline: 1.7028x; 1.4375x over previous
#include <cuda_runtime.h>
#include <cuda_bf16.h>
#include <math.h>
#include <cstdint>

#define BB   4
#define NPTS 16384
#define MPTS 4096
#define C1   128
#define C2   256
#define HCH  256
#define K1   384
#define NTOT (BB*NPTS)   // 65536

typedef unsigned long long u64;

// ---------------- mma / ldmatrix / cp.async helpers (sm_80+ baseline PTX) ----------------
__device__ __forceinline__ uint32_t smem_u32(const void* p) {
    uint32_t a;
    asm("{ .reg .u64 t; cvta.to.shared.u64 t, %1; cvt.u32.u64 %0, t; }" : "=r"(a) : "l"(p));
    return a;
}
__device__ __forceinline__ void ldsm4(uint32_t* r, uint32_t addr) {
    asm volatile("ldmatrix.sync.aligned.m8n8.x4.shared.b16 {%0,%1,%2,%3}, [%4];"
        : "=r"(r[0]), "=r"(r[1]), "=r"(r[2]), "=r"(r[3]) : "r"(addr));
}
__device__ __forceinline__ void mma_bf16(float* d, const uint32_t* a, const uint32_t* b) {
    asm volatile("mma.sync.aligned.m16n8k16.row.col.f32.bf16.bf16.f32 "
        "{%0,%1,%2,%3}, {%4,%5,%6,%7}, {%8,%9}, {%0,%1,%2,%3};"
        : "+f"(d[0]), "+f"(d[1]), "+f"(d[2]), "+f"(d[3])
        : "r"(a[0]), "r"(a[1]), "r"(a[2]), "r"(a[3]), "r"(b[0]), "r"(b[1]));
}
__device__ __forceinline__ void cp16(uint32_t saddr, const void* gaddr) {
    asm volatile("cp.async.cg.shared.global [%0], [%1], 16;" :: "r"(saddr), "l"(gaddr));
}
#define CP_COMMIT() asm volatile("cp.async.commit_group;" ::: "memory")
#define CP_WAIT(n)  asm volatile("cp.async.wait_group %0;" :: "n"(n) : "memory")

// smem stage layout: Ah, Al, Bh, Bl each 128 rows x 40 bf16 (80B rows)
#define MAT_BYTES (128*80)
#define OFF_AH 0
#define OFF_AL (MAT_BYTES)
#define OFF_BH (2*MAT_BYTES)
#define OFF_BL (3*MAT_BYTES)
#define STAGE  (4*MAT_BYTES)     // 40960
#define SM_TOT (2*STAGE)         // 81920

// ---------------- scratch (device globals) ----------------
__device__ float g_kfT[(size_t)BB*MPTS*C2];                         // 16.8 MB point-major known feats
__device__ __align__(16) __nv_bfloat16 g_ah[(size_t)NTOT*K1];       // A1 hi (point-major)
__device__ __align__(16) __nv_bfloat16 g_al[(size_t)NTOT*K1];       // A1 lo
__device__ __align__(16) __nv_bfloat16 g_w1h[HCH*K1], g_w1l[HCH*K1];
__device__ __align__(16) __nv_bfloat16 g_w2h[HCH*HCH], g_w2l[HCH*HCH];
__device__ __align__(16) __nv_bfloat16 g_a2h[(size_t)NTOT*HCH];     // A2 hi
__device__ __align__(16) __nv_bfloat16 g_a2l[(size_t)NTOT*HCH];
__device__ float g_y1[(size_t)NTOT*HCH];                            // gemm1 out, point-major
__device__ float g_ps[NTOT*12];
__device__ int   g_pi[NTOT*12];
__device__ float g_sum1[HCH], g_sq1[HCH], g_scale1[HCH], g_shift1[HCH];
__device__ float g_sum2[HCH], g_sq2[HCH], g_scale2[HCH], g_shift2[HCH];

__device__ __forceinline__ void bsplit(float x, __nv_bfloat16& h, __nv_bfloat16& l) {
    h = __float2bfloat16_rn(x);
    l = __float2bfloat16_rn(x - __bfloat162float(h));
}

// ---------------- prep: kf transpose, W1/W2 bf16 split, uf transpose+split, zero stats ----------------
__global__ void prep_kernel(const float* __restrict__ kf,
                            const float* __restrict__ W1,
                            const float* __restrict__ W2,
                            const float* __restrict__ uf) {
    __shared__ float tile[32][33];
    int tx = threadIdx.x, ty = threadIdx.y;
    int b = blockIdx.z, y = blockIdx.y, x = blockIdx.x;
    int tid = ty * 32 + tx;

    if (y < 8) {                                     // kf [b][c][p] -> g_kfT [b][p][c]
        if (x >= MPTS/32) return;
        int p0 = x * 32, c0 = y * 32;
        const float* src = kf + (size_t)b * C2 * MPTS;
        float* dst = g_kfT + (size_t)b * MPTS * C2;
#pragma unroll
        for (int r = 0; r < 32; r += 8)
            tile[ty + r][tx] = src[(size_t)(c0 + ty + r) * MPTS + p0 + tx];
        __syncthreads();
#pragma unroll
        for (int r = 0; r < 32; r += 8)
            dst[(size_t)(p0 + ty + r) * C2 + c0 + tx] = tile[tx][ty + r];
    } else if (y == 8) {                             // W1 split (b==0)
        if (b != 0 || x >= (HCH*K1)/256) return;
        int i = x * 256 + tid;
        __nv_bfloat16 h, l; bsplit(W1[i], h, l);
        g_w1h[i] = h; g_w1l[i] = l;
    } else if (y == 9) {                             // W2 split
        if (b != 0 || x >= (HCH*HCH)/256) return;
        int i = x * 256 + tid;
        __nv_bfloat16 h, l; bsplit(W2[i], h, l);
        g_w2h[i] = h; g_w2l[i] = l;
    } else if (y == 10) {                            // zero stats
        if (b != 0 || x != 0) return;
        g_sum1[tid] = 0.f; g_sq1[tid] = 0.f;
        g_sum2[tid] = 0.f; g_sq2[tid] = 0.f;
    } else {                                         // uf [b][c][i] -> A[j][256+c] bf16 hi/lo
        int c0 = (y - 11) * 32, i0 = x * 32;
        const float* src = uf + (size_t)b * C1 * NPTS;
#pragma unroll
        for (int r = 0; r < 32; r += 8)
            tile[ty + r][tx] = src[(size_t)(c0 + ty + r) * NPTS + i0 + tx];
        __syncthreads();
#pragma unroll
        for (int r = 0; r < 32; r += 8) {
            int j = b * NPTS + i0 + ty + r;
            float v = tile[tx][ty + r];
            __nv_bfloat16 h, l; bsplit(v, h, l);
            g_ah[(size_t)j * K1 + C2 + c0 + tx] = h;
            g_al[(size_t)j * K1 + C2 + c0 + tx] = l;
        }
    }
}

// ---------------- split-m 3-NN partials ----------------
__global__ void __launch_bounds__(128) three_nn_partial_kernel(
        const float* __restrict__ unknown, const float* __restrict__ known) {
    int tid = threadIdx.x;
    int g = blockIdx.x * 128 + tid;
    int t = blockIdx.y;
    int b = g >> 14;

    __shared__ float4 sk[1024];
    const float* kb = known + ((size_t)b * MPTS + t * 1024) * 3;
    for (int q = tid; q < 1024; q += 128) {
        float x = kb[q*3+0], y = kb[q*3+1], z = kb[q*3+2];
        sk[q] = make_float4(x, y, z, x*x + y*y + z*z);
    }
    __syncthreads();

    float ux = unknown[g*3+0], uy = unknown[g*3+1], uz = unknown[g*3+2];
    float ca = -2.f * ux, cb = -2.f * uy, cc = -2.f * uz;
    float s0 = 3.4e38f, s1 = 3.4e38f, s2 = 3.4e38f;
    int   i0 = 0, i1 = 0, i2 = 0;
#pragma unroll 8
    for (int jj = 0; jj < 1024; jj++) {
        float4 k4 = sk[jj];
        float s = fmaf(k4.x, ca, fmaf(k4.y, cb, fmaf(k4.z, cc, k4.w)));
        if (s < s2) {
            if (s < s1) {
                s2 = s1; i2 = i1;
                if (s < s0) { s1 = s0; i1 = i0; s0 = s; i0 = jj; }
                else        { s1 = s;  i1 = jj; }
            } else { s2 = s; i2 = jj; }
        }
    }
    int base = t * 1024;
    int o = g * 12 + t * 3;
    g_ps[o+0] = s0; g_ps[o+1] = s1; g_ps[o+2] = s2;
    g_pi[o+0] = base + i0; g_pi[o+1] = base + i1; g_pi[o+2] = base + i2;
}

// ---------------- merge + gather + interpolate -> A[j][0..255] bf16 hi/lo ----------------
__global__ void __launch_bounds__(256) interp_bf16_kernel(const float* __restrict__ unknown) {
    int warp = threadIdx.x >> 5, lane = threadIdx.x & 31;
    int g = blockIdx.x * 8 + warp;
    int b = g >> 14;

    float sl = (lane < 12) ? g_ps[g*12 + lane] : 3.4e38f;
    int   il = (lane < 12) ? g_pi[g*12 + lane] : 0;
    float s0 = 3.4e38f, s1 = 3.4e38f, s2 = 3.4e38f;
    int   i0 = 0, i1 = 0, i2 = 0;
#pragma unroll
    for (int j = 0; j < 12; j++) {
        float sj = __shfl_sync(0xffffffffu, sl, j);
        int   ij = __shfl_sync(0xffffffffu, il, j);
        if (sj < s2) {
            if (sj < s1) {
                s2 = s1; i2 = i1;
                if (sj < s0) { s1 = s0; i1 = i0; s0 = sj; i0 = ij; }
                else         { s1 = sj; i1 = ij; }
            } else { s2 = sj; i2 = ij; }
        }
    }
    float ux = unknown[g*3+0], uy = unknown[g*3+1], uz = unknown[g*3+2];
    float u2 = ux*ux + uy*uy + uz*uz;
    float d0 = s0 + u2, d1 = s1 + u2, d2 = s2 + u2;
    float r0 = 1.f / (d0 + 1e-8f), r1 = 1.f / (d1 + 1e-8f), r2 = 1.f / (d2 + 1e-8f);
    float rs = r0 + r1 + r2;
    float w0 = r0 / rs, w1 = r1 / rs, w2 = r2 / rs;

    const float4* f0 = (const float4*)&g_kfT[((size_t)(b*MPTS) + i0) * C2];
    const float4* f1 = (const float4*)&g_kfT[((size_t)(b*MPTS) + i1) * C2];
    const float4* f2 = (const float4*)&g_kfT[((size_t)(b*MPTS) + i2) * C2];

    float vals[8];
#pragma unroll
    for (int h = 0; h < 2; h++) {
        int v = lane*2 + h;
        float4 a = f0[v], c = f1[v], d = f2[v];
        vals[h*4+0] = fmaf(w0, a.x, fmaf(w1, c.x, w2 * d.x));
        vals[h*4+1] = fmaf(w0, a.y, fmaf(w1, c.y, w2 * d.y));
        vals[h*4+2] = fmaf(w0, a.z, fmaf(w1, c.z, w2 * d.z));
        vals[h*4+3] = fmaf(w0, a.w, fmaf(w1, c.w, w2 * d.w));
    }
    uint4 uh, ul;
    uint32_t* ph = (uint32_t*)&uh;
    uint32_t* pl = (uint32_t*)&ul;
#pragma unroll
    for (int q = 0; q < 4; q++) {
        __nv_bfloat16 h0, l0, h1, l1;
        bsplit(vals[q*2+0], h0, l0);
        bsplit(vals[q*2+1], h1, l1);
        __nv_bfloat162 hh = __nv_bfloat162(h0, h1);
        __nv_bfloat162 ll = __nv_bfloat162(l0, l1);
        ph[q] = *(uint32_t*)&hh;
        pl[q] = *(uint32_t*)&ll;
    }
    *(uint4*)(g_ah + (size_t)g * K1 + lane * 8) = uh;
    *(uint4*)(g_al + (size_t)g * K1 + lane * 8) = ul;
}

// ---------------- bf16x3 GEMM via mma.sync, 2-stage cp.async pipeline ----------------
// CTA: 128(j) x 128(o). 8 warps 4(m) x 2(n); warp tile 32x64 (2 x 8 m16n8k16).
// MODE 0: A=g_ah/g_al, B=g_w1h/l, K=384, store y1 point-major.
// MODE 1: A=g_a2h/l,  B=g_w2h/l, K=256, store channel-major to outp.
template<int KD, int MODE>
__global__ void __launch_bounds__(256) gemm_tc_kernel(float* __restrict__ outp) {
    extern __shared__ __align__(16) char smem[];
    const uint32_t su = smem_u32(smem);
    const int tid = threadIdx.x, lane = tid & 31, warp = tid >> 5;
    const int warp_m = warp >> 1, warp_n = warp & 1;
    const int j0 = blockIdx.x * 128, o0 = blockIdx.y * 128;

    const __nv_bfloat16 *Ah, *Al, *Bh, *Bl;
    if (MODE == 0) { Ah = g_ah;  Al = g_al;  Bh = g_w1h; Bl = g_w1l; }
    else           { Ah = g_a2h; Al = g_a2l; Bh = g_w2h; Bl = g_w2l; }

    const int NCH = KD / 32;
    // loader indices: 2 iterations x 256 threads cover 128 rows x 4 col-groups (8 bf16 each)
    int lrow0 = tid >> 2, lcg = (tid & 3) * 8;          // iter 0: rows 0..63
    // (iter t: row = lrow0 + t*64)

    // per-lane ldmatrix offsets (within a stage)
    uint32_t a_off[2], b_off[4];
#pragma unroll
    for (int mt = 0; mt < 2; mt++)
        a_off[mt] = (uint32_t)((warp_m*32 + mt*16 + (lane & 15)) * 80 + ((lane >> 4) << 3) * 2);
#pragma unroll
    for (int np = 0; np < 4; np++)
        b_off[np] = (uint32_t)((warp_n*64 + np*16 + (lane & 7) + ((lane >> 4) << 3)) * 80
                               + (((lane >> 3) & 1) << 3) * 2);

    float acc[2][8][4];
#pragma unroll
    for (int mt = 0; mt < 2; mt++)
#pragma unroll
        for (int nt = 0; nt < 8; nt++)
#pragma unroll
            for (int q = 0; q < 4; q++) acc[mt][nt][q] = 0.f;

    // prefetch chunk 0
    {
        uint32_t sb = su;
#pragma unroll
        for (int t = 0; t < 2; t++) {
            int row = lrow0 + t * 64;
            uint32_t so = (uint32_t)(row * 80 + lcg * 2);
            cp16(sb + OFF_AH + so, Ah + (size_t)(j0 + row) * KD + lcg);
            cp16(sb + OFF_AL + so, Al + (size_t)(j0 + row) * KD + lcg);
            cp16(sb + OFF_BH + so, Bh + (size_t)(o0 + row) * KD + lcg);
            cp16(sb + OFF_BL + so, Bl + (size_t)(o0 + row) * KD + lcg);
        }
        CP_COMMIT();
    }

    for (int ch = 0; ch < NCH; ch++) {
        if (ch + 1 < NCH) {
            int kc = (ch + 1) * 32;
            uint32_t sb = su + ((ch + 1) & 1) * STAGE;
#pragma unroll
            for (int t = 0; t < 2; t++) {
                int row = lrow0 + t * 64;
                uint32_t so = (uint32_t)(row * 80 + lcg * 2);
                cp16(sb + OFF_AH + so, Ah + (size_t)(j0 + row) * KD + kc + lcg);
                cp16(sb + OFF_AL + so, Al + (size_t)(j0 + row) * KD + kc + lcg);
                cp16(sb + OFF_BH + so, Bh + (size_t)(o0 + row) * KD + kc + lcg);
                cp16(sb + OFF_BL + so, Bl + (size_t)(o0 + row) * KD + kc + lcg);
            }
            CP_COMMIT();
            CP_WAIT(1);
        } else {
            CP_WAIT(0);
        }
        __syncthreads();

        uint32_t sb = su + (ch & 1) * STAGE;
#pragma unroll
        for (int ks = 0; ks < 32; ks += 16) {
            uint32_t Ahf[2][4], Alf[2][4], Bf[4][4];
#pragma unroll
            for (int mt = 0; mt < 2; mt++) {
                ldsm4(Ahf[mt], sb + OFF_AH + a_off[mt] + ks*2);
                ldsm4(Alf[mt], sb + OFF_AL + a_off[mt] + ks*2);
            }
#pragma unroll
            for (int np = 0; np < 4; np++)
                ldsm4(Bf[np], sb + OFF_BH + b_off[np] + ks*2);
            // hh + lh (Bh resident)
#pragma unroll
            for (int mt = 0; mt < 2; mt++)
#pragma unroll
                for (int nt = 0; nt < 8; nt++)
                    mma_bf16(acc[mt][nt], Ahf[mt], &Bf[nt >> 1][(nt & 1) * 2]);
#pragma unroll
            for (int mt = 0; mt < 2; mt++)
#pragma unroll
                for (int nt = 0; nt < 8; nt++)
                    mma_bf16(acc[mt][nt], Alf[mt], &Bf[nt >> 1][(nt & 1) * 2]);
            // hl (load Bl over Bh regs)
#pragma unroll
            for (int np = 0; np < 4; np++)
                ldsm4(Bf[np], sb + OFF_BL + b_off[np] + ks*2);
#pragma unroll
            for (int mt = 0; mt < 2; mt++)
#pragma unroll
                for (int nt = 0; nt < 8; nt++)
                    mma_bf16(acc[mt][nt], Ahf[mt], &Bf[nt >> 1][(nt & 1) * 2]);
        }
        __syncthreads();
    }

    if (MODE == 0) {
        // point-major y1[j][o]
#pragma unroll
        for (int mt = 0; mt < 2; mt++) {
            int j = j0 + warp_m*32 + mt*16 + (lane >> 2);
#pragma unroll
            for (int nt = 0; nt < 8; nt++) {
                int o = o0 + warp_n*64 + nt*8 + (lane & 3) * 2;
                *(float2*)&g_y1[(size_t)j * HCH + o]       = make_float2(acc[mt][nt][0], acc[mt][nt][1]);
                *(float2*)&g_y1[(size_t)(j + 8) * HCH + o] = make_float2(acc[mt][nt][2], acc[mt][nt][3]);
            }
        }
    } else {
        // channel-major out via smem transpose, 2 chunks of 64 o-rows
        int b = j0 >> 14, i0 = j0 & (NPTS - 1);
        float* tp = (float*)smem;                        // [64][132]
        for (int c = 0; c < 2; c++) {
            __syncthreads();
            if (warp_n == c) {
#pragma unroll
                for (int mt = 0; mt < 2; mt++) {
                    int jl = warp_m*32 + mt*16 + (lane >> 2);
#pragma unroll
                    for (int nt = 0; nt < 8; nt++) {
                        int ol = nt*8 + (lane & 3) * 2;
                        tp[ol * 132 + jl]           = acc[mt][nt][0];
                        tp[(ol + 1) * 132 + jl]     = acc[mt][nt][1];
                        tp[ol * 132 + jl + 8]       = acc[mt][nt][2];
                        tp[(ol + 1) * 132 + jl + 8] = acc[mt][nt][3];
                    }
                }
            }
            __syncthreads();
            int r = tid >> 2, part = tid & 3;
            int o = o0 + c*64 + r;
            float* dst = outp + ((size_t)(b * HCH + o)) * NPTS + i0 + part * 32;
            const float* srcr = tp + r * 132 + part * 32;
#pragma unroll
            for (int i = 0; i < 8; i++)
                *(float4*)(dst + i * 4) = make_float4(srcr[i*4+0], srcr[i*4+1], srcr[i*4+2], srcr[i*4+3]);
        }
    }
}

// per-channel sums over y1 (point-major)
__global__ void stats1_kernel() {
    int o = threadIdx.x;
    size_t j0 = (size_t)blockIdx.x * 256;
    const float* p = g_y1 + j0 * HCH + o;
    float s = 0.f, q = 0.f;
    for (int r = 0; r < 256; r++) {
        float v = p[(size_t)r * HCH];
        s += v; q = fmaf(v, v, q);
    }
    atomicAdd(&g_sum1[o], s);
    atomicAdd(&g_sq1[o], q);
}

__global__ void finalize_kernel(const float* __restrict__ gamma,
                                const float* __restrict__ beta,
                                int which) {
    int o = threadIdx.x;
    const float invN = 1.f / (float)NTOT;
    float s  = (which == 1) ? g_sum1[o] : g_sum2[o];
    float q  = (which == 1) ? g_sq1[o]  : g_sq2[o];
    float mu  = s * invN;
    float var = q * invN - mu * mu;
    float sc  = gamma[o] * rsqrtf(var + 1e-5f);
    float sh  = fmaf(-mu, sc, beta[o]);
    if (which == 1) { g_scale1[o] = sc; g_shift1[o] = sh; }
    else            { g_scale2[o] = sc; g_shift2[o] = sh; }
}

// y1 -> relu(bn1) -> bf16 hi/lo (point-major [j][256])
__global__ void conv_act2_kernel() {
    size_t t = (size_t)blockIdx.x * 256 + threadIdx.x;   // float4 index
    int ob = (int)(t & 63) * 4;
    float4 v = ((const float4*)g_y1)[t];
    float x0 = fmaxf(0.f, fmaf(v.x, g_scale1[ob+0], g_shift1[ob+0]));
    float x1 = fmaxf(0.f, fmaf(v.y, g_scale1[ob+1], g_shift1[ob+1]));
    float x2 = fmaxf(0.f, fmaf(v.z, g_scale1[ob+2], g_shift1[ob+2]));
    float x3 = fmaxf(0.f, fmaf(v.w, g_scale1[ob+3], g_shift1[ob+3]));
    __nv_bfloat16 h0,l0,h1,l1,h2,l2,h3,l3;
    bsplit(x0,h0,l0); bsplit(x1,h1,l1); bsplit(x2,h2,l2); bsplit(x3,h3,l3);
    __nv_bfloat162 ha = __nv_bfloat162(h0,h1), hb = __nv_bfloat162(h2,h3);
    __nv_bfloat162 la = __nv_bfloat162(l0,l1), lb = __nv_bfloat162(l2,l3);
    uint2 uh = make_uint2(*(uint32_t*)&ha, *(uint32_t*)&hb);
    uint2 ul = make_uint2(*(uint32_t*)&la, *(uint32_t*)&lb);
    *(uint2*)(g_a2h + t * 4) = uh;
    *(uint2*)(g_a2l + t * 4) = ul;
}

// per-channel sums over channel-major raw output
__global__ void stats2_kernel(const float* __restrict__ y2) {
    int row = blockIdx.x;
    int o = row & 255;
    const float* p = y2 + (size_t)row * NPTS;
    float s = 0.f, q = 0.f;
    for (int i = threadIdx.x; i < NPTS; i += 256) {
        float v = p[i];
        s += v; q = fmaf(v, v, q);
    }
    __shared__ float ss[256], sq[256];
    ss[threadIdx.x] = s; sq[threadIdx.x] = q;
    __syncthreads();
    for (int w = 128; w > 0; w >>= 1) {
        if (threadIdx.x < w) { ss[threadIdx.x] += ss[threadIdx.x+w]; sq[threadIdx.x] += sq[threadIdx.x+w]; }
        __syncthreads();
    }
    if (threadIdx.x == 0) {
        atomicAdd(&g_sum2[o], ss[0]);
        atomicAdd(&g_sq2[o], sq[0]);
    }
}

// in-place BN2 + ReLU on channel-major output
__global__ void bnrelu_out_kernel(float* __restrict__ out) {
    size_t t = (size_t)blockIdx.x * 256 + threadIdx.x;
    int o = (int)((t >> 12) & 255);
    float sc = g_scale2[o], sh = g_shift2[o];
    float4 v = ((float4*)out)[t];
    v.x = fmaxf(0.f, fmaf(v.x, sc, sh));
    v.y = fmaxf(0.f, fmaf(v.y, sc, sh));
    v.z = fmaxf(0.f, fmaf(v.z, sc, sh));
    v.w = fmaxf(0.f, fmaf(v.w, sc, sh));
    ((float4*)out)[t] = v;
}

// ---------------- launch ----------------
extern "C" void kernel_launch(void* const* d_in, const int* in_sizes, int n_in,
                              void* d_out, int out_size) {
    const float* unknown       = (const float*)d_in[0];
    const float* known         = (const float*)d_in[1];
    const float* unknown_feats = (const float*)d_in[2];
    const float* known_feats   = (const float*)d_in[3];
    const float* W1            = (const float*)d_in[4];
    const float* gamma1        = (const float*)d_in[5];
    const float* beta1         = (const float*)d_in[6];
    const float* W2            = (const float*)d_in[7];
    const float* gamma2        = (const float*)d_in[8];
    const float* beta2         = (const float*)d_in[9];
    float* out = (float*)d_out;

    cudaFuncSetAttribute(gemm_tc_kernel<K1, 0>, cudaFuncAttributeMaxDynamicSharedMemorySize, SM_TOT);
    cudaFuncSetAttribute(gemm_tc_kernel<HCH, 1>, cudaFuncAttributeMaxDynamicSharedMemorySize, SM_TOT);

    prep_kernel<<<dim3(512, 15, BB), dim3(32, 8)>>>(known_feats, W1, W2, unknown_feats);
    three_nn_partial_kernel<<<dim3(NTOT/128, 4), 128>>>(unknown, known);
    interp_bf16_kernel<<<NTOT/8, 256>>>(unknown);
    gemm_tc_kernel<K1, 0><<<dim3(NTOT/128, 2), 256, SM_TOT>>>(nullptr);   // ncu slot 4
    stats1_kernel<<<NTOT/256, 256>>>();
    finalize_kernel<<<1, 256>>>(gamma1, beta1, 1);
    conv_act2_kernel<<<(int)((size_t)NTOT*HCH/4/256), 256>>>();
    gemm_tc_kernel<HCH, 1><<<dim3(NTOT/128, 2), 256, SM_TOT>>>(out);
    stats2_kernel<<<BB*HCH, 256>>>(out);
    finalize_kernel<<<1, 256>>>(gamma2, beta2, 2);
    bnrelu_out_kernel<<<(int)((size_t)BB*HCH*(NPTS/4)/256), 256>>>(out);
}

// round 8
// speedup vs baseline: 1.8308x; 1.0752x over previous
#include <cuda_runtime.h>
#include <cuda_bf16.h>
#include <math.h>
#include <cstdint>

#define BB   4
#define NPTS 16384
#define MPTS 4096
#define C1   128
#define C2   256
#define HCH  256
#define K1   384
#define NTOT (BB*NPTS)   // 65536

typedef unsigned long long u64;

// ---------------- mma / ldmatrix / cp.async helpers (sm_80+ baseline PTX) ----------------
__device__ __forceinline__ uint32_t smem_u32(const void* p) {
    uint32_t a;
    asm("{ .reg .u64 t; cvta.to.shared.u64 t, %1; cvt.u32.u64 %0, t; }" : "=r"(a) : "l"(p));
    return a;
}
__device__ __forceinline__ void ldsm4(uint32_t* r, uint32_t addr) {
    asm volatile("ldmatrix.sync.aligned.m8n8.x4.shared.b16 {%0,%1,%2,%3}, [%4];"
        : "=r"(r[0]), "=r"(r[1]), "=r"(r[2]), "=r"(r[3]) : "r"(addr));
}
__device__ __forceinline__ void mma_bf16(float* d, const uint32_t* a, const uint32_t* b) {
    asm volatile("mma.sync.aligned.m16n8k16.row.col.f32.bf16.bf16.f32 "
        "{%0,%1,%2,%3}, {%4,%5,%6,%7}, {%8,%9}, {%0,%1,%2,%3};"
        : "+f"(d[0]), "+f"(d[1]), "+f"(d[2]), "+f"(d[3])
        : "r"(a[0]), "r"(a[1]), "r"(a[2]), "r"(a[3]), "r"(b[0]), "r"(b[1]));
}
__device__ __forceinline__ void cp16(uint32_t saddr, const void* gaddr) {
    asm volatile("cp.async.cg.shared.global [%0], [%1], 16;" :: "r"(saddr), "l"(gaddr));
}
#define CP_COMMIT() asm volatile("cp.async.commit_group;" ::: "memory")
#define CP_WAIT(n)  asm volatile("cp.async.wait_group %0;" :: "n"(n) : "memory")

// smem stage layout: Ah, Al, Bh, Bl each 128 rows x 40 bf16 (80B rows)
#define MAT_BYTES (128*80)
#define OFF_AH 0
#define OFF_AL (MAT_BYTES)
#define OFF_BH (2*MAT_BYTES)
#define OFF_BL (3*MAT_BYTES)
#define STAGE  (4*MAT_BYTES)     // 40960
#define SM_TOT (2*STAGE)         // 81920
#define BS_OFF (SM_TOT - 2048)   // stats scratch (256 floats+256 floats), safe after mainloop
                                 // MODE1 transpose buffer tp occupies [0 .. 64*132*4) = 33.8KB < BS_OFF

// ---------------- scratch (device globals) ----------------
__device__ float g_kfT[(size_t)BB*MPTS*C2];                         // 16.8 MB point-major known feats
__device__ __align__(16) __nv_bfloat16 g_ah[(size_t)NTOT*K1];       // A1 hi (point-major)
__device__ __align__(16) __nv_bfloat16 g_al[(size_t)NTOT*K1];       // A1 lo
__device__ __align__(16) __nv_bfloat16 g_w1h[HCH*K1], g_w1l[HCH*K1];
__device__ __align__(16) __nv_bfloat16 g_w2h[HCH*HCH], g_w2l[HCH*HCH];
__device__ __align__(16) __nv_bfloat16 g_a2h[(size_t)NTOT*HCH];     // A2 hi
__device__ __align__(16) __nv_bfloat16 g_a2l[(size_t)NTOT*HCH];
__device__ float g_y1[(size_t)NTOT*HCH];                            // gemm1 out, point-major
__device__ float g_ps[NTOT*12];
__device__ int   g_pi[NTOT*12];
__device__ float g_sum1[HCH], g_sq1[HCH], g_scale1[HCH], g_shift1[HCH];
__device__ float g_sum2[HCH], g_sq2[HCH], g_scale2[HCH], g_shift2[HCH];

__device__ __forceinline__ void bsplit(float x, __nv_bfloat16& h, __nv_bfloat16& l) {
    h = __float2bfloat16_rn(x);
    l = __float2bfloat16_rn(x - __bfloat162float(h));
}

// ---------------- prep: kf transpose, W1/W2 bf16 split, uf transpose+split, zero stats ----------------
__global__ void prep_kernel(const float* __restrict__ kf,
                            const float* __restrict__ W1,
                            const float* __restrict__ W2,
                            const float* __restrict__ uf) {
    __shared__ float tile[32][33];
    int tx = threadIdx.x, ty = threadIdx.y;
    int b = blockIdx.z, y = blockIdx.y, x = blockIdx.x;
    int tid = ty * 32 + tx;

    if (y < 8) {                                     // kf [b][c][p] -> g_kfT [b][p][c]
        if (x >= MPTS/32) return;
        int p0 = x * 32, c0 = y * 32;
        const float* src = kf + (size_t)b * C2 * MPTS;
        float* dst = g_kfT + (size_t)b * MPTS * C2;
#pragma unroll
        for (int r = 0; r < 32; r += 8)
            tile[ty + r][tx] = src[(size_t)(c0 + ty + r) * MPTS + p0 + tx];
        __syncthreads();
#pragma unroll
        for (int r = 0; r < 32; r += 8)
            dst[(size_t)(p0 + ty + r) * C2 + c0 + tx] = tile[tx][ty + r];
    } else if (y == 8) {                             // W1 split (b==0)
        if (b != 0 || x >= (HCH*K1)/256) return;
        int i = x * 256 + tid;
        __nv_bfloat16 h, l; bsplit(W1[i], h, l);
        g_w1h[i] = h; g_w1l[i] = l;
    } else if (y == 9) {                             // W2 split
        if (b != 0 || x >= (HCH*HCH)/256) return;
        int i = x * 256 + tid;
        __nv_bfloat16 h, l; bsplit(W2[i], h, l);
        g_w2h[i] = h; g_w2l[i] = l;
    } else if (y == 10) {                            // zero stats
        if (b != 0 || x != 0) return;
        g_sum1[tid] = 0.f; g_sq1[tid] = 0.f;
        g_sum2[tid] = 0.f; g_sq2[tid] = 0.f;
    } else {                                         // uf [b][c][i] -> A[j][256+c] bf16 hi/lo
        int c0 = (y - 11) * 32, i0 = x * 32;
        const float* src = uf + (size_t)b * C1 * NPTS;
#pragma unroll
        for (int r = 0; r < 32; r += 8)
            tile[ty + r][tx] = src[(size_t)(c0 + ty + r) * NPTS + i0 + tx];
        __syncthreads();
#pragma unroll
        for (int r = 0; r < 32; r += 8) {
            int j = b * NPTS + i0 + ty + r;
            float v = tile[tx][ty + r];
            __nv_bfloat16 h, l; bsplit(v, h, l);
            g_ah[(size_t)j * K1 + C2 + c0 + tx] = h;
            g_al[(size_t)j * K1 + C2 + c0 + tx] = l;
        }
    }
}

// ---------------- split-m 3-NN partials, 2 points per thread ----------------
// grid (NTOT/256, 4), block 128: block covers 256 points, tile of 1024 knowns.
__global__ void __launch_bounds__(128) three_nn_partial_kernel(
        const float* __restrict__ unknown, const float* __restrict__ known) {
    int tid = threadIdx.x;
    int gA = blockIdx.x * 256 + tid;
    int gB = gA + 128;
    int t = blockIdx.y;
    int b = gA >> 14;

    __shared__ float4 sk[1024];
    const float* kb = known + ((size_t)b * MPTS + t * 1024) * 3;
    for (int q = tid; q < 1024; q += 128) {
        float x = kb[q*3+0], y = kb[q*3+1], z = kb[q*3+2];
        sk[q] = make_float4(x, y, z, x*x + y*y + z*z);
    }
    __syncthreads();

    float ax = unknown[gA*3+0], ay = unknown[gA*3+1], az = unknown[gA*3+2];
    float bx = unknown[gB*3+0], by = unknown[gB*3+1], bz = unknown[gB*3+2];
    float caA = -2.f*ax, cbA = -2.f*ay, ccA = -2.f*az;
    float caB = -2.f*bx, cbB = -2.f*by, ccB = -2.f*bz;

    float a0 = 3.4e38f, a1 = 3.4e38f, a2 = 3.4e38f;
    float b0 = 3.4e38f, b1 = 3.4e38f, b2 = 3.4e38f;
    int   ia0 = 0, ia1 = 0, ia2 = 0, ib0 = 0, ib1 = 0, ib2 = 0;

#pragma unroll 4
    for (int jj = 0; jj < 1024; jj++) {
        float4 k4 = sk[jj];
        float s = fmaf(k4.x, caA, fmaf(k4.y, cbA, fmaf(k4.z, ccA, k4.w)));
        float u = fmaf(k4.x, caB, fmaf(k4.y, cbB, fmaf(k4.z, ccB, k4.w)));
        if (s < a2) {
            if (s < a1) {
                a2 = a1; ia2 = ia1;
                if (s < a0) { a1 = a0; ia1 = ia0; a0 = s; ia0 = jj; }
                else        { a1 = s;  ia1 = jj; }
            } else { a2 = s; ia2 = jj; }
        }
        if (u < b2) {
            if (u < b1) {
                b2 = b1; ib2 = ib1;
                if (u < b0) { b1 = b0; ib1 = ib0; b0 = u; ib0 = jj; }
                else        { b1 = u;  ib1 = jj; }
            } else { b2 = u; ib2 = jj; }
        }
    }
    int base = t * 1024;
    int oA = gA * 12 + t * 3, oB = gB * 12 + t * 3;
    g_ps[oA+0] = a0; g_ps[oA+1] = a1; g_ps[oA+2] = a2;
    g_pi[oA+0] = base + ia0; g_pi[oA+1] = base + ia1; g_pi[oA+2] = base + ia2;
    g_ps[oB+0] = b0; g_ps[oB+1] = b1; g_ps[oB+2] = b2;
    g_pi[oB+0] = base + ib0; g_pi[oB+1] = base + ib1; g_pi[oB+2] = base + ib2;
}

// ---------------- merge + gather + interpolate -> A[j][0..255] bf16 hi/lo ----------------
__global__ void __launch_bounds__(256) interp_bf16_kernel(const float* __restrict__ unknown) {
    int warp = threadIdx.x >> 5, lane = threadIdx.x & 31;
    int g = blockIdx.x * 8 + warp;
    int b = g >> 14;

    float sl = (lane < 12) ? g_ps[g*12 + lane] : 3.4e38f;
    int   il = (lane < 12) ? g_pi[g*12 + lane] : 0;
    float s0 = 3.4e38f, s1 = 3.4e38f, s2 = 3.4e38f;
    int   i0 = 0, i1 = 0, i2 = 0;
#pragma unroll
    for (int j = 0; j < 12; j++) {
        float sj = __shfl_sync(0xffffffffu, sl, j);
        int   ij = __shfl_sync(0xffffffffu, il, j);
        if (sj < s2) {
            if (sj < s1) {
                s2 = s1; i2 = i1;
                if (sj < s0) { s1 = s0; i1 = i0; s0 = sj; i0 = ij; }
                else         { s1 = sj; i1 = ij; }
            } else { s2 = sj; i2 = ij; }
        }
    }
    float ux = unknown[g*3+0], uy = unknown[g*3+1], uz = unknown[g*3+2];
    float u2 = ux*ux + uy*uy + uz*uz;
    float d0 = s0 + u2, d1 = s1 + u2, d2 = s2 + u2;
    float r0 = 1.f / (d0 + 1e-8f), r1 = 1.f / (d1 + 1e-8f), r2 = 1.f / (d2 + 1e-8f);
    float rs = r0 + r1 + r2;
    float w0 = r0 / rs, w1 = r1 / rs, w2 = r2 / rs;

    const float4* f0 = (const float4*)&g_kfT[((size_t)(b*MPTS) + i0) * C2];
    const float4* f1 = (const float4*)&g_kfT[((size_t)(b*MPTS) + i1) * C2];
    const float4* f2 = (const float4*)&g_kfT[((size_t)(b*MPTS) + i2) * C2];

    float vals[8];
#pragma unroll
    for (int h = 0; h < 2; h++) {
        int v = lane*2 + h;
        float4 a = f0[v], c = f1[v], d = f2[v];
        vals[h*4+0] = fmaf(w0, a.x, fmaf(w1, c.x, w2 * d.x));
        vals[h*4+1] = fmaf(w0, a.y, fmaf(w1, c.y, w2 * d.y));
        vals[h*4+2] = fmaf(w0, a.z, fmaf(w1, c.z, w2 * d.z));
        vals[h*4+3] = fmaf(w0, a.w, fmaf(w1, c.w, w2 * d.w));
    }
    uint4 uh, ul;
    uint32_t* ph = (uint32_t*)&uh;
    uint32_t* pl = (uint32_t*)&ul;
#pragma unroll
    for (int q = 0; q < 4; q++) {
        __nv_bfloat16 h0, l0, h1, l1;
        bsplit(vals[q*2+0], h0, l0);
        bsplit(vals[q*2+1], h1, l1);
        __nv_bfloat162 hh = __nv_bfloat162(h0, h1);
        __nv_bfloat162 ll = __nv_bfloat162(l0, l1);
        ph[q] = *(uint32_t*)&hh;
        pl[q] = *(uint32_t*)&ll;
    }
    *(uint4*)(g_ah + (size_t)g * K1 + lane * 8) = uh;
    *(uint4*)(g_al + (size_t)g * K1 + lane * 8) = ul;
}

// ---------------- bf16x3 GEMM via mma.sync, 2-stage cp.async pipeline, fused BN stats ----------------
// CTA: 128(j) x 128(o). 8 warps 4(m) x 2(n); warp tile 32x64 (2 x 8 m16n8k16).
// MODE 0: A=g_ah/g_al, B=g_w1h/l, K=384, store y1 point-major, stats -> g_sum1/g_sq1.
// MODE 1: A=g_a2h/l,  B=g_w2h/l, K=256, store channel-major to outp, stats -> g_sum2/g_sq2.
template<int KD, int MODE>
__global__ void __launch_bounds__(256, 2) gemm_tc_kernel(float* __restrict__ outp) {
    extern __shared__ __align__(16) char smem[];
    const uint32_t su = smem_u32(smem);
    const int tid = threadIdx.x, lane = tid & 31, warp = tid >> 5;
    const int warp_m = warp >> 1, warp_n = warp & 1;
    const int j0 = blockIdx.x * 128, o0 = blockIdx.y * 128;

    const __nv_bfloat16 *Ah, *Al, *Bh, *Bl;
    if (MODE == 0) { Ah = g_ah;  Al = g_al;  Bh = g_w1h; Bl = g_w1l; }
    else           { Ah = g_a2h; Al = g_a2l; Bh = g_w2h; Bl = g_w2l; }

    const int NCH = KD / 32;
    int lrow0 = tid >> 2, lcg = (tid & 3) * 8;

    uint32_t a_off[2], b_off[4];
#pragma unroll
    for (int mt = 0; mt < 2; mt++)
        a_off[mt] = (uint32_t)((warp_m*32 + mt*16 + (lane & 15)) * 80 + ((lane >> 4) << 3) * 2);
#pragma unroll
    for (int np = 0; np < 4; np++)
        b_off[np] = (uint32_t)((warp_n*64 + np*16 + (lane & 7) + ((lane >> 4) << 3)) * 80
                               + (((lane >> 3) & 1) << 3) * 2);

    float acc[2][8][4];
#pragma unroll
    for (int mt = 0; mt < 2; mt++)
#pragma unroll
        for (int nt = 0; nt < 8; nt++)
#pragma unroll
            for (int q = 0; q < 4; q++) acc[mt][nt][q] = 0.f;

    // prefetch chunk 0
    {
        uint32_t sb = su;
#pragma unroll
        for (int t = 0; t < 2; t++) {
            int row = lrow0 + t * 64;
            uint32_t so = (uint32_t)(row * 80 + lcg * 2);
            cp16(sb + OFF_AH + so, Ah + (size_t)(j0 + row) * KD + lcg);
            cp16(sb + OFF_AL + so, Al + (size_t)(j0 + row) * KD + lcg);
            cp16(sb + OFF_BH + so, Bh + (size_t)(o0 + row) * KD + lcg);
            cp16(sb + OFF_BL + so, Bl + (size_t)(o0 + row) * KD + lcg);
        }
        CP_COMMIT();
    }

    for (int ch = 0; ch < NCH; ch++) {
        if (ch + 1 < NCH) {
            int kc = (ch + 1) * 32;
            uint32_t sb = su + ((ch + 1) & 1) * STAGE;
#pragma unroll
            for (int t = 0; t < 2; t++) {
                int row = lrow0 + t * 64;
                uint32_t so = (uint32_t)(row * 80 + lcg * 2);
                cp16(sb + OFF_AH + so, Ah + (size_t)(j0 + row) * KD + kc + lcg);
                cp16(sb + OFF_AL + so, Al + (size_t)(j0 + row) * KD + kc + lcg);
                cp16(sb + OFF_BH + so, Bh + (size_t)(o0 + row) * KD + kc + lcg);
                cp16(sb + OFF_BL + so, Bl + (size_t)(o0 + row) * KD + kc + lcg);
            }
            CP_COMMIT();
            CP_WAIT(1);
        } else {
            CP_WAIT(0);
        }
        __syncthreads();

        uint32_t sb = su + (ch & 1) * STAGE;
#pragma unroll
        for (int ks = 0; ks < 32; ks += 16) {
            uint32_t Ahf[2][4], Alf[2][4], Bhf[4][4], Blf[4][4];
#pragma unroll
            for (int mt = 0; mt < 2; mt++) {
                ldsm4(Ahf[mt], sb + OFF_AH + a_off[mt] + ks*2);
                ldsm4(Alf[mt], sb + OFF_AL + a_off[mt] + ks*2);
            }
#pragma unroll
            for (int np = 0; np < 4; np++)
                ldsm4(Bhf[np], sb + OFF_BH + b_off[np] + ks*2);
#pragma unroll
            for (int np = 0; np < 4; np++)
                ldsm4(Blf[np], sb + OFF_BL + b_off[np] + ks*2);
#pragma unroll
            for (int mt = 0; mt < 2; mt++)
#pragma unroll
                for (int nt = 0; nt < 8; nt++)
                    mma_bf16(acc[mt][nt], Ahf[mt], &Bhf[nt >> 1][(nt & 1) * 2]);
#pragma unroll
            for (int mt = 0; mt < 2; mt++)
#pragma unroll
                for (int nt = 0; nt < 8; nt++)
                    mma_bf16(acc[mt][nt], Alf[mt], &Bhf[nt >> 1][(nt & 1) * 2]);
#pragma unroll
            for (int mt = 0; mt < 2; mt++)
#pragma unroll
                for (int nt = 0; nt < 8; nt++)
                    mma_bf16(acc[mt][nt], Ahf[mt], &Blf[nt >> 1][(nt & 1) * 2]);
        }
        __syncthreads();
    }

    // ---- fused per-channel stats from accumulators ----
    {
        float* bsm = (float*)(smem + BS_OFF);
        float* bqm = bsm + 128;
        if (tid < 128) { bsm[tid] = 0.f; bqm[tid] = 0.f; }
        __syncthreads();
#pragma unroll
        for (int nt = 0; nt < 8; nt++) {
            float se = 0.f, so = 0.f, qe = 0.f, qo = 0.f;
#pragma unroll
            for (int mt = 0; mt < 2; mt++) {
                float v0 = acc[mt][nt][0], v1 = acc[mt][nt][1];
                float v2 = acc[mt][nt][2], v3 = acc[mt][nt][3];
                se += v0 + v2; so += v1 + v3;
                qe = fmaf(v0, v0, fmaf(v2, v2, qe));
                qo = fmaf(v1, v1, fmaf(v3, v3, qo));
            }
#pragma unroll
            for (int m = 4; m <= 16; m <<= 1) {
                se += __shfl_xor_sync(0xffffffffu, se, m);
                so += __shfl_xor_sync(0xffffffffu, so, m);
                qe += __shfl_xor_sync(0xffffffffu, qe, m);
                qo += __shfl_xor_sync(0xffffffffu, qo, m);
            }
            if ((lane >> 2) == 0) {
                int ol = warp_n*64 + nt*8 + (lane & 3) * 2;
                atomicAdd(&bsm[ol],     se);
                atomicAdd(&bqm[ol],     qe);
                atomicAdd(&bsm[ol + 1], so);
                atomicAdd(&bqm[ol + 1], qo);
            }
        }
        __syncthreads();
        if (tid < 128) {
            if (MODE == 0) {
                atomicAdd(&g_sum1[o0 + tid], bsm[tid]);
                atomicAdd(&g_sq1[o0 + tid],  bqm[tid]);
            } else {
                atomicAdd(&g_sum2[o0 + tid], bsm[tid]);
                atomicAdd(&g_sq2[o0 + tid],  bqm[tid]);
            }
        }
    }

    if (MODE == 0) {
        // point-major y1[j][o]
#pragma unroll
        for (int mt = 0; mt < 2; mt++) {
            int j = j0 + warp_m*32 + mt*16 + (lane >> 2);
#pragma unroll
            for (int nt = 0; nt < 8; nt++) {
                int o = o0 + warp_n*64 + nt*8 + (lane & 3) * 2;
                *(float2*)&g_y1[(size_t)j * HCH + o]       = make_float2(acc[mt][nt][0], acc[mt][nt][1]);
                *(float2*)&g_y1[(size_t)(j + 8) * HCH + o] = make_float2(acc[mt][nt][2], acc[mt][nt][3]);
            }
        }
    } else {
        // channel-major out via smem transpose, 2 chunks of 64 o-rows
        int b = j0 >> 14, i0 = j0 & (NPTS - 1);
        float* tp = (float*)smem;                        // [64][132] = 33.8KB < BS_OFF
        for (int c = 0; c < 2; c++) {
            __syncthreads();
            if (warp_n == c) {
#pragma unroll
                for (int mt = 0; mt < 2; mt++) {
                    int jl = warp_m*32 + mt*16 + (lane >> 2);
#pragma unroll
                    for (int nt = 0; nt < 8; nt++) {
                        int ol = nt*8 + (lane & 3) * 2;
                        tp[ol * 132 + jl]           = acc[mt][nt][0];
                        tp[(ol + 1) * 132 + jl]     = acc[mt][nt][1];
                        tp[ol * 132 + jl + 8]       = acc[mt][nt][2];
                        tp[(ol + 1) * 132 + jl + 8] = acc[mt][nt][3];
                    }
                }
            }
            __syncthreads();
            int r = tid >> 2, part = tid & 3;
            int o = o0 + c*64 + r;
            float* dst = outp + ((size_t)(b * HCH + o)) * NPTS + i0 + part * 32;
            const float* srcr = tp + r * 132 + part * 32;
#pragma unroll
            for (int i = 0; i < 8; i++)
                *(float4*)(dst + i * 4) = make_float4(srcr[i*4+0], srcr[i*4+1], srcr[i*4+2], srcr[i*4+3]);
        }
    }
}

__global__ void finalize_kernel(const float* __restrict__ gamma,
                                const float* __restrict__ beta,
                                int which) {
    int o = threadIdx.x;
    const float invN = 1.f / (float)NTOT;
    float s  = (which == 1) ? g_sum1[o] : g_sum2[o];
    float q  = (which == 1) ? g_sq1[o]  : g_sq2[o];
    float mu  = s * invN;
    float var = q * invN - mu * mu;
    float sc  = gamma[o] * rsqrtf(var + 1e-5f);
    float sh  = fmaf(-mu, sc, beta[o]);
    if (which == 1) { g_scale1[o] = sc; g_shift1[o] = sh; }
    else            { g_scale2[o] = sc; g_shift2[o] = sh; }
}

// y1 -> relu(bn1) -> bf16 hi/lo (point-major [j][256])
__global__ void conv_act2_kernel() {
    size_t t = (size_t)blockIdx.x * 256 + threadIdx.x;   // float4 index
    int ob = (int)(t & 63) * 4;
    float4 v = ((const float4*)g_y1)[t];
    float x0 = fmaxf(0.f, fmaf(v.x, g_scale1[ob+0], g_shift1[ob+0]));
    float x1 = fmaxf(0.f, fmaf(v.y, g_scale1[ob+1], g_shift1[ob+1]));
    float x2 = fmaxf(0.f, fmaf(v.z, g_scale1[ob+2], g_shift1[ob+2]));
    float x3 = fmaxf(0.f, fmaf(v.w, g_scale1[ob+3], g_shift1[ob+3]));
    __nv_bfloat16 h0,l0,h1,l1,h2,l2,h3,l3;
    bsplit(x0,h0,l0); bsplit(x1,h1,l1); bsplit(x2,h2,l2); bsplit(x3,h3,l3);
    __nv_bfloat162 ha = __nv_bfloat162(h0,h1), hb = __nv_bfloat162(h2,h3);
    __nv_bfloat162 la = __nv_bfloat162(l0,l1), lb = __nv_bfloat162(l2,l3);
    uint2 uh = make_uint2(*(uint32_t*)&ha, *(uint32_t*)&hb);
    uint2 ul = make_uint2(*(uint32_t*)&la, *(uint32_t*)&lb);
    *(uint2*)(g_a2h + t * 4) = uh;
    *(uint2*)(g_a2l + t * 4) = ul;
}

// in-place BN2 + ReLU on channel-major output
__global__ void bnrelu_out_kernel(float* __restrict__ out) {
    size_t t = (size_t)blockIdx.x * 256 + threadIdx.x;
    int o = (int)((t >> 12) & 255);
    float sc = g_scale2[o], sh = g_shift2[o];
    float4 v = ((float4*)out)[t];
    v.x = fmaxf(0.f, fmaf(v.x, sc, sh));
    v.y = fmaxf(0.f, fmaf(v.y, sc, sh));
    v.z = fmaxf(0.f, fmaf(v.z, sc, sh));
    v.w = fmaxf(0.f, fmaf(v.w, sc, sh));
    ((float4*)out)[t] = v;
}

// ---------------- launch ----------------
extern "C" void kernel_launch(void* const* d_in, const int* in_sizes, int n_in,
                              void* d_out, int out_size) {
    const float* unknown       = (const float*)d_in[0];
    const float* known         = (const float*)d_in[1];
    const float* unknown_feats = (const float*)d_in[2];
    const float* known_feats   = (const float*)d_in[3];
    const float* W1            = (const float*)d_in[4];
    const float* gamma1        = (const float*)d_in[5];
    const float* beta1         = (const float*)d_in[6];
    const float* W2            = (const float*)d_in[7];
    const float* gamma2        = (const float*)d_in[8];
    const float* beta2         = (const float*)d_in[9];
    float* out = (float*)d_out;

    cudaFuncSetAttribute(gemm_tc_kernel<K1, 0>, cudaFuncAttributeMaxDynamicSharedMemorySize, SM_TOT);
    cudaFuncSetAttribute(gemm_tc_kernel<HCH, 1>, cudaFuncAttributeMaxDynamicSharedMemorySize, SM_TOT);

    prep_kernel<<<dim3(512, 15, BB), dim3(32, 8)>>>(known_feats, W1, W2, unknown_feats);
    three_nn_partial_kernel<<<dim3(NTOT/256, 4), 128>>>(unknown, known);
    interp_bf16_kernel<<<NTOT/8, 256>>>(unknown);
    gemm_tc_kernel<K1, 0><<<dim3(NTOT/128, 2), 256, SM_TOT>>>(nullptr);   // ncu slot 4
    finalize_kernel<<<1, 256>>>(gamma1, beta1, 1);
    conv_act2_kernel<<<(int)((size_t)NTOT*HCH/4/256), 256>>>();
    gemm_tc_kernel<HCH, 1><<<dim3(NTOT/128, 2), 256, SM_TOT>>>(out);
    finalize_kernel<<<1, 256>>>(gamma2, beta2, 2);
    bnrelu_out_kernel<<<(int)((size_t)BB*HCH*(NPTS/4)/256), 256>>>(out);
}